// round 12
// baseline (speedup 1.0000x reference)
#include <cuda_runtime.h>
#include <cuda_fp16.h>
#include <stdint.h>

// ============================================================================
//   h_e = relu(x[row]@W1a + x[col]@W1b + ea@W1c + b1)
//   g0: u = x@W1a + b1, v = x@W1b (dense per node, fp16)
//   g1: h = relu(u[row] + v[col] + ea@W1c); hsum[row] += h (coalesced red)
//   g2: out[n] = hsum[n]@W2 + degf[n]*b2
// fp16 mma.sync.m16n8k16, f32 accumulate.
// ============================================================================
#define E_TOTAL   640000
#define NN_NODES  100000
#define OUT_ELEMS (NN_NODES * 128)
#define TILE_E    128
#define N_TILES   (E_TOTAL / TILE_E)   // 5000
#define GRID_MAIN 148
#define N_TILES0  1563                 // ceil(100000/64)
#define N_TILES2  782                  // ceil(100000/128)

// g0 SMEM
#define G0_A    0        // [8 planes][64 rows][8 words] = 16384 B
#define G0_WA   16384    // 65536 B
#define G0_WB   81920    // 65536 B
#define G0_B1   147456   // 256 floats
#define SMEM_G0 148480

// g1 SMEM
#define G1_ROWS 0        // 128 int
#define G1_COLS 512      // 128 int
#define G1_WC   1024     // [4][256][8] words = 32768 B
#define G1_AEA  33792    // [4][128][8] words = 16384 B
#define G1_UV   50176    // 128 rows x 132 words x 4 B = 67584 B
#define SMEM_G1 117760

// g2 SMEM
#define F_B2_OFF   0
#define F_ABUF_OFF 1024  // 2 x 8192
#define F_W2_OFF   17408 // 65536
#define SMEM_FIN   82944

// ============================================================================
// Device scratch (allocation-free)
// ============================================================================
__device__ __align__(16) __half g_Wa[8 * 2048 * 2];
__device__ __align__(16) __half g_Wb[8 * 2048 * 2];
__device__ __align__(16) __half g_Wc[4 * 2048 * 2];
__device__ __align__(16) __half g_W2h[8 * 4096];
__device__ __align__(16) __half g_u[NN_NODES * 256];
__device__ __align__(16) __half g_v[NN_NODES * 256];
__device__ __align__(16) float  g_hsum[NN_NODES * 256];
__device__ float g_degf[NN_NODES];
__device__ int   g_is64;

// ============================================================================
// Helpers
// ============================================================================
__device__ __forceinline__ uint32_t f2h2(float lo, float hi) {
    uint32_t r;
    asm("cvt.rn.f16x2.f32 %0, %1, %2;" : "=r"(r) : "f"(hi), "f"(lo));
    return r;
}
__device__ __forceinline__ uint32_t hadd2u(uint32_t a, uint32_t b) {
    uint32_t r;
    asm("add.rn.f16x2 %0, %1, %2;" : "=r"(r) : "r"(a), "r"(b));
    return r;
}
__device__ __forceinline__ void mma16(float* d, const uint32_t* a,
                                      uint32_t b0, uint32_t b1) {
    asm volatile(
        "mma.sync.aligned.m16n8k16.row.col.f32.f16.f16.f32 "
        "{%0,%1,%2,%3}, {%4,%5,%6,%7}, {%8,%9}, {%0,%1,%2,%3};"
        : "+f"(d[0]), "+f"(d[1]), "+f"(d[2]), "+f"(d[3])
        : "r"(a[0]), "r"(a[1]), "r"(a[2]), "r"(a[3]), "r"(b0), "r"(b1));
}
__device__ __forceinline__ void red2(float* p, float v0, float v1) {
    asm volatile("red.global.add.v2.f32 [%0], {%1, %2};"
                 :: "l"(p), "f"(v0), "f"(v1) : "memory");
}
__device__ __forceinline__ void red1(float* p, float v) {
    asm volatile("red.global.add.f32 [%0], %1;" :: "l"(p), "f"(v) : "memory");
}

// Stage 16 consecutive k-values (one k16 plane) of one row into an operand
// image. word = ks*stride + row*8 + ((2s)^z) + hi, z = (row&4) ^ ((ks&1)<<1).
__device__ __forceinline__ void stage_row(uint32_t* ab, int row, int ks,
                                          int stride, const float4* v) {
    uint32_t* rp = ab + ks * stride + row * 8;
    const int z = (row & 4) ^ ((ks & 1) << 1);
    *(uint2*)&rp[0 ^ z] = make_uint2(f2h2(v[0].x, v[0].y), f2h2(v[2].x, v[2].y));
    *(uint2*)&rp[2 ^ z] = make_uint2(f2h2(v[0].z, v[0].w), f2h2(v[2].z, v[2].w));
    *(uint2*)&rp[4 ^ z] = make_uint2(f2h2(v[1].x, v[1].y), f2h2(v[3].x, v[3].y));
    *(uint2*)&rp[6 ^ z] = make_uint2(f2h2(v[1].z, v[1].w), f2h2(v[3].z, v[3].w));
}

// Matching weight-image element store (setup side).
__device__ __forceinline__ void img_store(__half* img, int kk, int n,
                                          int plane_words, float val) {
    const int ks = kk >> 4, w = (kk & 15) >> 1;
    const int z = (n & 4) ^ ((ks & 1) << 1);
    const int word = ks * plane_words + n * 8 + ((2 * (w & 3)) ^ z) + (w >> 2);
    img[word * 2 + (kk & 1)] = __float2half_rn(val);
}

// ============================================================================
// Setup
// ============================================================================
#define SETUP_BLOCKS 25840
__global__ void setup_kernel(const void* ei, const float* __restrict__ W1,
                             const float* __restrict__ W2) {
    int i = blockIdx.x * 256 + threadIdx.x;
    if (i < 6400000) {
        ((float4*)g_hsum)[i] = make_float4(0.f, 0.f, 0.f, 0.f);
        return;
    }
    i -= 6400000;
    if (i < NN_NODES) { g_degf[i] = 0.f; return; }
    i -= NN_NODES;
    if (i < 32768) {                       // W1a
        int kk = i >> 8, n = i & 255;
        img_store(g_Wa, kk, n, 2048, W1[kk * 256 + n]);
    } else if (i < 65536) {                // W1b
        int j = i - 32768;
        int kk = j >> 8, n = j & 255;
        img_store(g_Wb, kk, n, 2048, W1[(kk + 128) * 256 + n]);
    } else if (i < 81920) {                // W1c
        int j = i - 65536;
        int kk = j >> 8, n = j & 255;
        img_store(g_Wc, kk, n, 2048, W1[(kk + 256) * 256 + n]);
    } else if (i < 114688) {               // W2
        int j = i - 81920;
        int k = j >> 7, n = j & 127;
        img_store(g_W2h + (k >> 5) * 4096, k & 31, n, 1024, W2[k * 128 + n]);
    } else if (i == 114688) {
        const unsigned* w = (const unsigned*)ei;
        int is64 = 1;
        for (int t = 0; t < 64; t++)
            if (w[2 * t + 1] != 0) { is64 = 0; break; }
        g_is64 = is64;
    }
}

// ============================================================================
// g0: u[n] = fp16(x[n]@W1a + b1), v[n] = fp16(x[n]@W1b).
// ============================================================================
__global__ void __launch_bounds__(256, 1)
edgeconv_g0(const float* __restrict__ x, const float* __restrict__ b1) {
    extern __shared__ char smem[];
    const int tid  = threadIdx.x;
    const int wid  = tid >> 5;
    const int lane = tid & 31;
    const int gq   = lane >> 2;
    const int q2   = 2 * (lane & 3);
    const int zn   = gq & 4;
    const int rowg = wid & 1;
    const int colh = (wid >> 1) & 1;
    const int outs = wid >> 2;

    {
        const float4* sa = (const float4*)g_Wa;
        const float4* sb = (const float4*)g_Wb;
        float4* da = (float4*)(smem + G0_WA);
        float4* db = (float4*)(smem + G0_WB);
        #pragma unroll
        for (int i = 0; i < 16; i++) {
            da[tid + i * 256] = sa[tid + i * 256];
            db[tid + i * 256] = sb[tid + i * 256];
        }
        ((float*)(smem + G0_B1))[tid] = b1[tid];
    }
    __syncthreads();

    float2 b1v[16];
    #pragma unroll
    for (int nt = 0; nt < 16; nt++)
        b1v[nt] = *(const float2*)((float*)(smem + G0_B1) +
                                   128 * colh + 8 * nt + 2 * (lane & 3));

    const int rbase = 32 * rowg + gq;
    const int e   = tid >> 2;
    const int sub = tid & 3;
    uint32_t* Axw = (uint32_t*)(smem + G0_A);
    const uint32_t* Wim = (const uint32_t*)(smem + (outs ? G0_WB : G0_WA));

    for (int tile = blockIdx.x; tile < N_TILES0; tile += GRID_MAIN) {
        const int grow = tile * 64 + e;
        const bool gok = grow < NN_NODES;
        __syncthreads();
        #pragma unroll
        for (int pi = 0; pi < 2; pi++) {
            const int p = 2 * sub + pi;
            float4 v[4];
            const float* sp = x + (size_t)grow * 128 + p * 16;
            #pragma unroll
            for (int j = 0; j < 4; j++)
                v[j] = gok ? *(const float4*)(sp + j * 4) : make_float4(0, 0, 0, 0);
            stage_row(Axw, e, p, 512, v);
        }
        __syncthreads();

        float acc[2][16][4];
        #pragma unroll
        for (int mt = 0; mt < 2; mt++)
            #pragma unroll
            for (int nt = 0; nt < 16; nt++) {
                float bx = outs ? 0.f : b1v[nt].x;
                float by = outs ? 0.f : b1v[nt].y;
                acc[mt][nt][0] = bx; acc[mt][nt][1] = by;
                acc[mt][nt][2] = bx; acc[mt][nt][3] = by;
            }

        #pragma unroll
        for (int ks = 0; ks < 8; ks++) {
            const uint32_t* Aks = Axw + ks * 512;
            const uint32_t* Bks = Wim + ks * 2048;
            const int qz = q2 ^ zn ^ ((ks & 1) << 1);
            uint32_t af[2][4];
            #pragma unroll
            for (int mt = 0; mt < 2; mt++) {
                const int r0 = rbase + 16 * mt;
                uint2 lo = *(const uint2*)&Aks[r0 * 8 + qz];
                uint2 hi = *(const uint2*)&Aks[(r0 + 8) * 8 + qz];
                af[mt][0] = lo.x; af[mt][1] = hi.x;
                af[mt][2] = lo.y; af[mt][3] = hi.y;
            }
            #pragma unroll
            for (int nt = 0; nt < 16; nt++) {
                const int n = 128 * colh + 8 * nt + gq;
                uint2 bv = *(const uint2*)&Bks[n * 8 + qz];
                #pragma unroll
                for (int mt = 0; mt < 2; mt++) mma16(acc[mt][nt], af[mt], bv.x, bv.y);
            }
        }

        __half* outp = outs ? g_v : g_u;
        #pragma unroll
        for (int mt = 0; mt < 2; mt++) {
            const int r0 = tile * 64 + rbase + 16 * mt;
            #pragma unroll
            for (int nt = 0; nt < 16; nt++) {
                const int cn = 128 * colh + 8 * nt + 2 * (lane & 3);
                if (r0 < NN_NODES)
                    *(uint32_t*)(outp + (size_t)r0 * 256 + cn) =
                        f2h2(acc[mt][nt][0], acc[mt][nt][1]);
                if (r0 + 8 < NN_NODES)
                    *(uint32_t*)(outp + (size_t)(r0 + 8) * 256 + cn) =
                        f2h2(acc[mt][nt][2], acc[mt][nt][3]);
            }
        }
    }
}

// ============================================================================
// g1: acc = ea@W1c; h = relu(acc + u[row] + v[col]) (fp16, staged in-place in
//     UV); coalesced warp-per-row scatter: hsum[rows[e]] += h, degf += 1.
// UV: 128 rows x 132-word stride; row r word w -> bank (4r+w)&31: gather
// stores, epilogue LDS/STS.32, scatter LDS.32 all conflict-free.
// ============================================================================
__global__ void __launch_bounds__(256, 1)
edgeconv_g1(const void* __restrict__ ei, const float* __restrict__ ea) {
    extern __shared__ char smem[];
    const int tid  = threadIdx.x;
    const int wid  = tid >> 5;
    const int lane = tid & 31;
    const int gq   = lane >> 2;
    const int q2   = 2 * (lane & 3);
    const int zn   = gq & 4;
    const int wr   = wid >> 2;   // rows [64wr, +64)
    const int wc   = wid & 3;    // cols [64wc, +64)
    const int is64 = g_is64;

    int* rows_s = (int*)(smem + G1_ROWS);
    int* cols_s = (int*)(smem + G1_COLS);
    uint32_t* WC  = (uint32_t*)(smem + G1_WC);
    uint32_t* AEA = (uint32_t*)(smem + G1_AEA);
    uint32_t* UV  = (uint32_t*)(smem + G1_UV);

    {   // resident W1c image (32 KB)
        const float4* src = (const float4*)g_Wc;
        float4* dst = (float4*)(smem + G1_WC);
        #pragma unroll
        for (int i = 0; i < 8; i++) dst[tid + i * 256] = src[tid + i * 256];
    }

    const int rbase = 64 * wr + gq;
    const int e  = tid >> 1;
    const int h  = tid & 1;

    for (int tile = blockIdx.x; tile < N_TILES; tile += GRID_MAIN) {
        const int ebase = tile * TILE_E;
        __syncthreads();   // prior tile scatter done with UV / indices
        if (tid < 128) {
            if (is64) {
                rows_s[tid] = (int)((const long long*)ei)[ebase + tid];
                cols_s[tid] = (int)((const long long*)ei)[E_TOTAL + ebase + tid];
            } else {
                rows_s[tid] = ((const int*)ei)[ebase + tid];
                cols_s[tid] = ((const int*)ei)[E_TOTAL + ebase + tid];
            }
        }
        __syncthreads();

        // stage ea chunk (contiguous rows -> coalesced)
        #pragma unroll
        for (int pi = 0; pi < 2; pi++) {
            const int p = 2 * h + pi;
            float4 v[4];
            const float* sp = ea + (size_t)(ebase + e) * 64 + p * 16;
            #pragma unroll
            for (int j = 0; j < 4; j++) v[j] = *(const float4*)(sp + j * 4);
            stage_row(AEA, e, p, 1024, v);
        }
        // uv gather: warp-per-row (one LDG.128 covers one full 512B row)
        {
            #pragma unroll 4
            for (int t = 0; t < 16; t++) {
                const int ee = 16 * wid + t;
                const __half* up = g_u + (size_t)rows_s[ee] * 256 + lane * 8;
                const __half* vp = g_v + (size_t)cols_s[ee] * 256 + lane * 8;
                uint4 a = *(const uint4*)up;
                uint4 b = *(const uint4*)vp;
                uint4 r;
                r.x = hadd2u(a.x, b.x); r.y = hadd2u(a.y, b.y);
                r.z = hadd2u(a.z, b.z); r.w = hadd2u(a.w, b.w);
                *(uint4*)(UV + ee * 132 + lane * 4) = r;
            }
        }
        __syncthreads();

        // ea GEMM: K=64 -> 4 k16 planes
        float acc[4][8][4];
        #pragma unroll
        for (int mt = 0; mt < 4; mt++)
            #pragma unroll
            for (int nt = 0; nt < 8; nt++)
                #pragma unroll
                for (int i = 0; i < 4; i++) acc[mt][nt][i] = 0.f;

        #pragma unroll
        for (int ks = 0; ks < 4; ks++) {
            const uint32_t* Aks = AEA + ks * 1024;
            const uint32_t* Bks = WC + ks * 2048;
            const int qz = q2 ^ zn ^ ((ks & 1) << 1);
            uint32_t af[4][4];
            #pragma unroll
            for (int mt = 0; mt < 4; mt++) {
                const int r0 = rbase + 16 * mt;
                uint2 lo = *(const uint2*)&Aks[r0 * 8 + qz];
                uint2 hi = *(const uint2*)&Aks[(r0 + 8) * 8 + qz];
                af[mt][0] = lo.x; af[mt][1] = hi.x;
                af[mt][2] = lo.y; af[mt][3] = hi.y;
            }
            #pragma unroll
            for (int nt = 0; nt < 8; nt++) {
                const int n = 64 * wc + 8 * nt + gq;
                uint2 bv = *(const uint2*)&Bks[n * 8 + qz];
                #pragma unroll
                for (int mt = 0; mt < 4; mt++) mma16(acc[mt][nt], af[mt], bv.x, bv.y);
            }
        }

        // epilogue: h = relu(acc + uv), fp16, written in-place into UV.
        // Each word is read+written by exactly one thread -> no hazard.
        #pragma unroll
        for (int mt = 0; mt < 4; mt++) {
            const int r0 = rbase + 16 * mt;
            #pragma unroll
            for (int nt = 0; nt < 8; nt++) {
                const int widx = 32 * wc + 4 * nt + (lane & 3);
                uint32_t* p0 = UV + r0 * 132 + widx;
                uint32_t* p1 = UV + (r0 + 8) * 132 + widx;
                float2 f0 = __half22float2(*(const __half2*)p0);
                float2 f1 = __half22float2(*(const __half2*)p1);
                *p0 = f2h2(fmaxf(acc[mt][nt][0] + f0.x, 0.f),
                           fmaxf(acc[mt][nt][1] + f0.y, 0.f));
                *p1 = f2h2(fmaxf(acc[mt][nt][2] + f1.x, 0.f),
                           fmaxf(acc[mt][nt][3] + f1.y, 0.f));
            }
        }
        __syncthreads();

        // scatter: warp-per-row, fully coalesced red2 (256B per instruction)
        #pragma unroll 2
        for (int t = 0; t < 16; t++) {
            const int r = 16 * wid + t;
            float* dst = g_hsum + (size_t)rows_s[r] * 256;
            #pragma unroll
            for (int k = 0; k < 4; k++) {
                uint32_t word = UV[r * 132 + 32 * k + lane];
                float2 f = __half22float2(*(const __half2*)&word);
                red2(dst + 64 * k + 2 * lane, f.x, f.y);
            }
            if (lane == 0) red1(g_degf + rows_s[r], 1.0f);
        }
    }
}

// ============================================================================
// g2: out[n,:] = fp16(hsum[n]) @ W2 + degf[n]*b2
// ============================================================================
__global__ void __launch_bounds__(256, 1)
edgeconv_g2(const float* __restrict__ b2, float* __restrict__ out) {
    extern __shared__ char smem[];
    const int tid  = threadIdx.x;
    const int wid  = tid >> 5;
    const int lane = tid & 31;
    const int wr   = wid >> 1;
    const int wc   = wid & 1;
    const int gq   = lane >> 2;
    const int q2   = 2 * (lane & 3);
    const int zn   = gq & 4;

    float* sB2 = (float*)(smem + F_B2_OFF);
    if (tid < 128) sB2[tid] = b2[tid];
    {
        const float4* src = (const float4*)g_W2h;
        float4* dst = (float4*)(smem + F_W2_OFF);
        #pragma unroll
        for (int i = 0; i < 16; i++) dst[tid + i * 256] = src[tid + i * 256];
    }
    __syncthreads();

    float2 b2v[8];
    #pragma unroll
    for (int nt = 0; nt < 8; nt++)
        b2v[nt] = *(const float2*)&sB2[64 * wc + 8 * nt + 2 * (lane & 3)];

    const int rbase = 32 * wr + gq;
    const int e     = tid >> 1;
    const int half  = tid & 1;

    for (int tile = blockIdx.x; tile < N_TILES2; tile += GRID_MAIN) {
        const int rg = tile * 128 + e;
        const bool ok = rg < NN_NODES;
        float4 v[4];
        {
            const float* p = g_hsum + (size_t)rg * 256 + half * 16;
            #pragma unroll
            for (int j = 0; j < 4; j++)
                v[j] = ok ? *(const float4*)(p + j * 4) : make_float4(0, 0, 0, 0);
            stage_row((uint32_t*)(smem + F_ABUF_OFF), e, half, 1024, v);
            p = g_hsum + (size_t)rg * 256 + 32 + half * 16;
            #pragma unroll
            for (int j = 0; j < 4; j++)
                v[j] = ok ? *(const float4*)(p + j * 4) : make_float4(0, 0, 0, 0);
        }
        __syncthreads();

        float acc[2][8][4];
        #pragma unroll
        for (int mt = 0; mt < 2; mt++)
            #pragma unroll
            for (int nt = 0; nt < 8; nt++)
                #pragma unroll
                for (int i = 0; i < 4; i++) acc[mt][nt][i] = 0.f;

        #pragma unroll 1
        for (int j = 0; j < 8; j++) {
            const int s = j & 1;
            const uint32_t* A16 = (const uint32_t*)(smem + F_ABUF_OFF + s * 8192);
            const uint32_t* B16 = (const uint32_t*)(smem + F_W2_OFF + j * 8192);
            #pragma unroll
            for (int ks = 0; ks < 2; ks++) {
                const uint32_t* Aks = A16 + ks * 1024;
                const uint32_t* Bks = B16 + ks * 1024;
                const int qz = q2 ^ zn ^ (ks << 1);
                uint32_t af[2][4];
                #pragma unroll
                for (int mt = 0; mt < 2; mt++) {
                    const int r0 = rbase + 16 * mt;
                    uint2 lo = *(const uint2*)&Aks[r0 * 8 + qz];
                    uint2 hi = *(const uint2*)&Aks[(r0 + 8) * 8 + qz];
                    af[mt][0] = lo.x; af[mt][1] = hi.x;
                    af[mt][2] = lo.y; af[mt][3] = hi.y;
                }
                #pragma unroll
                for (int nt = 0; nt < 8; nt++) {
                    const int n = 64 * wc + 8 * nt + gq;
                    uint2 bv = *(const uint2*)&Bks[n * 8 + qz];
                    #pragma unroll
                    for (int mt = 0; mt < 2; mt++) mma16(acc[mt][nt], af[mt], bv.x, bv.y);
                }
            }
            if (j < 7) {
                stage_row((uint32_t*)(smem + F_ABUF_OFF + (s ^ 1) * 8192), e, half, 1024, v);
                if (j < 6) {
                    const float* p = g_hsum + (size_t)rg * 256 + (j + 2) * 32 + half * 16;
                    #pragma unroll
                    for (int jj = 0; jj < 4; jj++)
                        v[jj] = ok ? *(const float4*)(p + jj * 4) : make_float4(0, 0, 0, 0);
                }
            }
            __syncthreads();
        }

        #pragma unroll
        for (int mt = 0; mt < 2; mt++) {
            const int r0 = tile * 128 + rbase + 16 * mt;
            const bool ok0 = r0 < NN_NODES;
            const bool ok1 = (r0 + 8) < NN_NODES;
            const float dg0 = ok0 ? g_degf[r0] : 0.f;
            const float dg1 = ok1 ? g_degf[r0 + 8] : 0.f;
            #pragma unroll
            for (int nt = 0; nt < 8; nt++) {
                const int cn = 64 * wc + 8 * nt + 2 * (lane & 3);
                if (ok0) {
                    float2 o = make_float2(acc[mt][nt][0] + dg0 * b2v[nt].x,
                                           acc[mt][nt][1] + dg0 * b2v[nt].y);
                    *(float2*)(out + (size_t)r0 * 128 + cn) = o;
                }
                if (ok1) {
                    float2 o = make_float2(acc[mt][nt][2] + dg1 * b2v[nt].x,
                                           acc[mt][nt][3] + dg1 * b2v[nt].y);
                    *(float2*)(out + (size_t)(r0 + 8) * 128 + cn) = o;
                }
            }
        }
    }
}

// ============================================================================
// Launch
// ============================================================================
extern "C" void kernel_launch(void* const* d_in, const int* in_sizes, int n_in,
                              void* d_out, int out_size) {
    const float* x  = (const float*)d_in[0];
    const void*  ei = d_in[1];
    const float* ea = (const float*)d_in[2];
    const float* W1 = (const float*)d_in[3];
    const float* b1 = (const float*)d_in[4];
    const float* W2 = (const float*)d_in[5];
    const float* b2 = (const float*)d_in[6];
    float* out = (float*)d_out;

    cudaFuncSetAttribute(edgeconv_g0,
                         cudaFuncAttributeMaxDynamicSharedMemorySize, SMEM_G0);
    cudaFuncSetAttribute(edgeconv_g1,
                         cudaFuncAttributeMaxDynamicSharedMemorySize, SMEM_G1);
    cudaFuncSetAttribute(edgeconv_g2,
                         cudaFuncAttributeMaxDynamicSharedMemorySize, SMEM_FIN);

    setup_kernel<<<SETUP_BLOCKS, 256>>>(ei, W1, W2);
    edgeconv_g0<<<GRID_MAIN, 256, SMEM_G0>>>(x, b1);
    edgeconv_g1<<<GRID_MAIN, 256, SMEM_G1>>>(ei, ea);
    edgeconv_g2<<<GRID_MAIN, 256, SMEM_FIN>>>(b2, out);
}

// round 13
// speedup vs baseline: 1.1286x; 1.1286x over previous
#include <cuda_runtime.h>
#include <cuda_fp16.h>
#include <stdint.h>

// ============================================================================
//   h_e = relu(x[row]@W1a + x[col]@W1b + ea@W1c + b1)
//   g0: u = x@W1a + b1, v = x@W1b (dense per node, fp16)
//   g1: edges processed in DEST-SORTED order (locality for u-gather + hsum RED)
//       h = relu(u[row] + v[col] + ea@W1c); hsum[row] += h
//   g2: out[n] = hsum[n]@W2 + degf[n]*b2
// fp16 mma.sync.m16n8k16, f32 accumulate.
// ============================================================================
#define E_TOTAL   640000
#define NN_NODES  100000
#define OUT_ELEMS (NN_NODES * 128)
#define TILE_E    128
#define N_TILES   (E_TOTAL / TILE_E)   // 5000
#define GRID_MAIN 148
#define N_TILES0  1563                 // ceil(100000/64)
#define N_TILES2  782                  // ceil(100000/128)
#define NCHUNKS   98                   // ceil(100000/1024) scan chunks

// g0 SMEM
#define G0_A    0        // [8 planes][64 rows][8 words] = 16384 B
#define G0_WA   16384    // 65536 B
#define G0_WB   81920    // 65536 B
#define G0_B1   147456   // 256 floats
#define SMEM_G0 148480

// g1 SMEM
#define G1_ROWS 0        // 128 int
#define G1_COLS 512      // 128 int
#define G1_EIDX 1024     // 128 int
#define G1_WC   1536     // [4][256][8] words = 32768 B
#define G1_AEA  34304    // [4][128][8] words = 16384 B
#define G1_UV   50688    // 128 rows x 136 words x 4 B = 69632 B
#define SMEM_G1 120320

// g2 SMEM
#define F_B2_OFF   0
#define F_ABUF_OFF 1024  // 2 x 8192
#define F_W2_OFF   17408 // 65536
#define SMEM_FIN   82944

// ============================================================================
// Device scratch (allocation-free)
// ============================================================================
__device__ __align__(16) __half g_Wa[8 * 2048 * 2];
__device__ __align__(16) __half g_Wb[8 * 2048 * 2];
__device__ __align__(16) __half g_Wc[4 * 2048 * 2];
__device__ __align__(16) __half g_W2h[8 * 4096];
__device__ __align__(16) __half g_u[NN_NODES * 256];
__device__ __align__(16) __half g_v[NN_NODES * 256];
__device__ __align__(16) float  g_hsum[NN_NODES * 256];
__device__ float g_degf[NN_NODES];
__device__ int   g_is64;
// counting-sort scratch
__device__ int g_cnt[NN_NODES];      // histogram, then placement cursor
__device__ int g_off[NN_NODES];      // exclusive offsets
__device__ int g_blksum[NCHUNKS];    // scan partials
__device__ int g_rows_srt[E_TOTAL];
__device__ int g_cols_srt[E_TOTAL];
__device__ int g_eidx_srt[E_TOTAL];

// ============================================================================
// Helpers
// ============================================================================
__device__ __forceinline__ uint32_t f2h2(float lo, float hi) {
    uint32_t r;
    asm("cvt.rn.f16x2.f32 %0, %1, %2;" : "=r"(r) : "f"(hi), "f"(lo));
    return r;
}
__device__ __forceinline__ uint32_t hadd2u(uint32_t a, uint32_t b) {
    uint32_t r;
    asm("add.rn.f16x2 %0, %1, %2;" : "=r"(r) : "r"(a), "r"(b));
    return r;
}
__device__ __forceinline__ void mma16(float* d, const uint32_t* a,
                                      uint32_t b0, uint32_t b1) {
    asm volatile(
        "mma.sync.aligned.m16n8k16.row.col.f32.f16.f16.f32 "
        "{%0,%1,%2,%3}, {%4,%5,%6,%7}, {%8,%9}, {%0,%1,%2,%3};"
        : "+f"(d[0]), "+f"(d[1]), "+f"(d[2]), "+f"(d[3])
        : "r"(a[0]), "r"(a[1]), "r"(a[2]), "r"(a[3]), "r"(b0), "r"(b1));
}
__device__ __forceinline__ void red2(float* p, float v0, float v1) {
    asm volatile("red.global.add.v2.f32 [%0], {%1, %2};"
                 :: "l"(p), "f"(v0), "f"(v1) : "memory");
}
__device__ __forceinline__ int ld_idx(const void* ei, int pos) {
    return g_is64 ? (int)((const long long*)ei)[pos] : ((const int*)ei)[pos];
}

// Stage 16 consecutive k-values (one k16 plane) of one row into an operand
// image. word = ks*stride + row*8 + ((2s)^z) + hi, z = (row&4) ^ ((ks&1)<<1).
__device__ __forceinline__ void stage_row(uint32_t* ab, int row, int ks,
                                          int stride, const float4* v) {
    uint32_t* rp = ab + ks * stride + row * 8;
    const int z = (row & 4) ^ ((ks & 1) << 1);
    *(uint2*)&rp[0 ^ z] = make_uint2(f2h2(v[0].x, v[0].y), f2h2(v[2].x, v[2].y));
    *(uint2*)&rp[2 ^ z] = make_uint2(f2h2(v[0].z, v[0].w), f2h2(v[2].z, v[2].w));
    *(uint2*)&rp[4 ^ z] = make_uint2(f2h2(v[1].x, v[1].y), f2h2(v[3].x, v[3].y));
    *(uint2*)&rp[6 ^ z] = make_uint2(f2h2(v[1].z, v[1].w), f2h2(v[3].z, v[3].w));
}

// Matching weight-image element store (setup side).
__device__ __forceinline__ void img_store(__half* img, int kk, int n,
                                          int plane_words, float val) {
    const int ks = kk >> 4, w = (kk & 15) >> 1;
    const int z = (n & 4) ^ ((ks & 1) << 1);
    const int word = ks * plane_words + n * 8 + ((2 * (w & 3)) ^ z) + (w >> 2);
    img[word * 2 + (kk & 1)] = __float2half_rn(val);
}

// ============================================================================
// Setup + counting sort (hist -> scan x3 -> place)
// ============================================================================
#define SETUP_BLOCKS 25840
__global__ void setup_kernel(const void* ei, const float* __restrict__ W1,
                             const float* __restrict__ W2) {
    int i = blockIdx.x * 256 + threadIdx.x;
    if (i < 6400000) {
        ((float4*)g_hsum)[i] = make_float4(0.f, 0.f, 0.f, 0.f);
        return;
    }
    i -= 6400000;
    if (i < NN_NODES) { g_cnt[i] = 0; return; }
    i -= NN_NODES;
    if (i < 32768) {                       // W1a
        int kk = i >> 8, n = i & 255;
        img_store(g_Wa, kk, n, 2048, W1[kk * 256 + n]);
    } else if (i < 65536) {                // W1b
        int j = i - 32768;
        int kk = j >> 8, n = j & 255;
        img_store(g_Wb, kk, n, 2048, W1[(kk + 128) * 256 + n]);
    } else if (i < 81920) {                // W1c
        int j = i - 65536;
        int kk = j >> 8, n = j & 255;
        img_store(g_Wc, kk, n, 2048, W1[(kk + 256) * 256 + n]);
    } else if (i < 114688) {               // W2
        int j = i - 81920;
        int k = j >> 7, n = j & 127;
        img_store(g_W2h + (k >> 5) * 4096, k & 31, n, 1024, W2[k * 128 + n]);
    } else if (i == 114688) {              // int64 probe
        const unsigned* w = (const unsigned*)ei;
        int is64 = 1;
        for (int t = 0; t < 64; t++)
            if (w[2 * t + 1] != 0) { is64 = 0; break; }
        g_is64 = is64;
    }
}

__global__ void hist_kernel(const void* ei) {
    int e = blockIdx.x * 256 + threadIdx.x;
    if (e < E_TOTAL) atomicAdd(&g_cnt[ld_idx(ei, e)], 1);
}

__global__ void scan1_kernel() {   // per-chunk scan + degf
    __shared__ int s[1024];
    int g = blockIdx.x * 1024 + threadIdx.x;
    int v = (g < NN_NODES) ? g_cnt[g] : 0;
    s[threadIdx.x] = v;
    __syncthreads();
    #pragma unroll
    for (int d = 1; d < 1024; d <<= 1) {
        int t = (threadIdx.x >= d) ? s[threadIdx.x - d] : 0;
        __syncthreads();
        s[threadIdx.x] += t;
        __syncthreads();
    }
    if (g < NN_NODES) {
        g_off[g] = s[threadIdx.x] - v;     // exclusive within chunk
        g_degf[g] = (float)v;
    }
    if (threadIdx.x == 1023) g_blksum[blockIdx.x] = s[1023];
}

__global__ void scan2_kernel() {   // scan the 98 chunk totals
    if (threadIdx.x == 0) {
        int acc = 0;
        for (int i = 0; i < NCHUNKS; i++) {
            int t = g_blksum[i];
            g_blksum[i] = acc;
            acc += t;
        }
    }
}

__global__ void scan3_kernel() {   // add chunk base; init cursor
    int g = blockIdx.x * 256 + threadIdx.x;
    if (g < NN_NODES) {
        int o = g_off[g] + g_blksum[g >> 10];
        g_off[g] = o;
        g_cnt[g] = o;
    }
}

__global__ void place_kernel(const void* ei) {
    int e = blockIdx.x * 256 + threadIdx.x;
    if (e < E_TOTAL) {
        int r = ld_idx(ei, e);
        int c = ld_idx(ei, E_TOTAL + e);
        int pos = atomicAdd(&g_cnt[r], 1);
        g_rows_srt[pos] = r;
        g_cols_srt[pos] = c;
        g_eidx_srt[pos] = e;
    }
}

// ============================================================================
// g0: u[n] = fp16(x[n]@W1a + b1), v[n] = fp16(x[n]@W1b). (unchanged)
// ============================================================================
__global__ void __launch_bounds__(256, 1)
edgeconv_g0(const float* __restrict__ x, const float* __restrict__ b1) {
    extern __shared__ char smem[];
    const int tid  = threadIdx.x;
    const int wid  = tid >> 5;
    const int lane = tid & 31;
    const int gq   = lane >> 2;
    const int q2   = 2 * (lane & 3);
    const int zn   = gq & 4;
    const int rowg = wid & 1;
    const int colh = (wid >> 1) & 1;
    const int outs = wid >> 2;

    {
        const float4* sa = (const float4*)g_Wa;
        const float4* sb = (const float4*)g_Wb;
        float4* da = (float4*)(smem + G0_WA);
        float4* db = (float4*)(smem + G0_WB);
        #pragma unroll
        for (int i = 0; i < 16; i++) {
            da[tid + i * 256] = sa[tid + i * 256];
            db[tid + i * 256] = sb[tid + i * 256];
        }
        ((float*)(smem + G0_B1))[tid] = b1[tid];
    }
    __syncthreads();

    float2 b1v[16];
    #pragma unroll
    for (int nt = 0; nt < 16; nt++)
        b1v[nt] = *(const float2*)((float*)(smem + G0_B1) +
                                   128 * colh + 8 * nt + 2 * (lane & 3));

    const int rbase = 32 * rowg + gq;
    const int e   = tid >> 2;
    const int sub = tid & 3;
    uint32_t* Axw = (uint32_t*)(smem + G0_A);
    const uint32_t* Wim = (const uint32_t*)(smem + (outs ? G0_WB : G0_WA));

    for (int tile = blockIdx.x; tile < N_TILES0; tile += GRID_MAIN) {
        const int grow = tile * 64 + e;
        const bool gok = grow < NN_NODES;
        __syncthreads();
        #pragma unroll
        for (int pi = 0; pi < 2; pi++) {
            const int p = 2 * sub + pi;
            float4 v[4];
            const float* sp = x + (size_t)grow * 128 + p * 16;
            #pragma unroll
            for (int j = 0; j < 4; j++)
                v[j] = gok ? *(const float4*)(sp + j * 4) : make_float4(0, 0, 0, 0);
            stage_row(Axw, e, p, 512, v);
        }
        __syncthreads();

        float acc[2][16][4];
        #pragma unroll
        for (int mt = 0; mt < 2; mt++)
            #pragma unroll
            for (int nt = 0; nt < 16; nt++) {
                float bx = outs ? 0.f : b1v[nt].x;
                float by = outs ? 0.f : b1v[nt].y;
                acc[mt][nt][0] = bx; acc[mt][nt][1] = by;
                acc[mt][nt][2] = bx; acc[mt][nt][3] = by;
            }

        #pragma unroll
        for (int ks = 0; ks < 8; ks++) {
            const uint32_t* Aks = Axw + ks * 512;
            const uint32_t* Bks = Wim + ks * 2048;
            const int qz = q2 ^ zn ^ ((ks & 1) << 1);
            uint32_t af[2][4];
            #pragma unroll
            for (int mt = 0; mt < 2; mt++) {
                const int r0 = rbase + 16 * mt;
                uint2 lo = *(const uint2*)&Aks[r0 * 8 + qz];
                uint2 hi = *(const uint2*)&Aks[(r0 + 8) * 8 + qz];
                af[mt][0] = lo.x; af[mt][1] = hi.x;
                af[mt][2] = lo.y; af[mt][3] = hi.y;
            }
            #pragma unroll
            for (int nt = 0; nt < 16; nt++) {
                const int n = 128 * colh + 8 * nt + gq;
                uint2 bv = *(const uint2*)&Bks[n * 8 + qz];
                #pragma unroll
                for (int mt = 0; mt < 2; mt++) mma16(acc[mt][nt], af[mt], bv.x, bv.y);
            }
        }

        __half* outp = outs ? g_v : g_u;
        #pragma unroll
        for (int mt = 0; mt < 2; mt++) {
            const int r0 = tile * 64 + rbase + 16 * mt;
            #pragma unroll
            for (int nt = 0; nt < 16; nt++) {
                const int cn = 128 * colh + 8 * nt + 2 * (lane & 3);
                if (r0 < NN_NODES)
                    *(uint32_t*)(outp + (size_t)r0 * 256 + cn) =
                        f2h2(acc[mt][nt][0], acc[mt][nt][1]);
                if (r0 + 8 < NN_NODES)
                    *(uint32_t*)(outp + (size_t)(r0 + 8) * 256 + cn) =
                        f2h2(acc[mt][nt][2], acc[mt][nt][3]);
            }
        }
    }
}

// ============================================================================
// g1: R10 core, dest-sorted edges. acc = ea@W1c; h = relu(acc+u[row]+v[col]);
// hsum[row] += h. UV: 128 rows x 136 words, halves +0/+68, inner XOR (e&4).
// ============================================================================
__global__ void __launch_bounds__(256, 1)
edgeconv_g1(const float* __restrict__ ea) {
    extern __shared__ char smem[];
    const int tid  = threadIdx.x;
    const int wid  = tid >> 5;
    const int lane = tid & 31;
    const int gq   = lane >> 2;
    const int q2   = 2 * (lane & 3);
    const int zn   = gq & 4;
    const int wr   = wid >> 2;   // rows [64wr, +64)
    const int wc   = wid & 3;    // cols [64wc, +64)

    int* rows_s = (int*)(smem + G1_ROWS);
    int* cols_s = (int*)(smem + G1_COLS);
    int* eidx_s = (int*)(smem + G1_EIDX);
    uint32_t* WC  = (uint32_t*)(smem + G1_WC);
    uint32_t* AEA = (uint32_t*)(smem + G1_AEA);
    uint32_t* UV  = (uint32_t*)(smem + G1_UV);

    {   // resident W1c image (32 KB)
        const float4* src = (const float4*)g_Wc;
        float4* dst = (float4*)(smem + G1_WC);
        #pragma unroll
        for (int i = 0; i < 8; i++) dst[tid + i * 256] = src[tid + i * 256];
    }

    const int rbase = 64 * wr + gq;
    const int e  = tid >> 1;
    const int h  = tid & 1;
    const int e2 = (e >> 2) & 1;           // (e&4)>>2
    const int hh68 = 68 * (wc >> 1);
    const int wbase = 32 * (wc & 1) + (lane & 3);
    const int g4 = gq & 4;

    for (int tile = blockIdx.x; tile < N_TILES; tile += GRID_MAIN) {
        const int ebase = tile * TILE_E;
        __syncthreads();   // prior tile epilogue done with UV / indices
        if (tid < 128) {
            rows_s[tid] = g_rows_srt[ebase + tid];
            cols_s[tid] = g_cols_srt[ebase + tid];
            eidx_s[tid] = g_eidx_srt[ebase + tid];
        }
        __syncthreads();

        // stage ea chunk via sorted edge index
        #pragma unroll
        for (int pi = 0; pi < 2; pi++) {
            const int p = 2 * h + pi;
            float4 v[4];
            const float* sp = ea + (size_t)eidx_s[e] * 64 + p * 16;
            #pragma unroll
            for (int j = 0; j < 4; j++) v[j] = *(const float4*)(sp + j * 4);
            stage_row(AEA, e, p, 1024, v);
        }
        // stage uv = u[row]+v[col] (fp16): thread-per-edge-half (R10 layout)
        {
            const __half* up = g_u + (size_t)rows_s[e] * 256;
            const __half* vp = g_v + (size_t)cols_s[e] * 256;
            uint32_t* uvrow = UV + e * 136 + 68 * h;
            #pragma unroll
            for (int j = 0; j < 16; j++) {
                const int lg = 16 * h + (j ^ e2);
                uint4 a = *(const uint4*)(up + lg * 8);
                uint4 b = *(const uint4*)(vp + lg * 8);
                uint4 r;
                r.x = hadd2u(a.x, b.x); r.y = hadd2u(a.y, b.y);
                r.z = hadd2u(a.z, b.z); r.w = hadd2u(a.w, b.w);
                *(uint4*)(uvrow + 4 * j) = r;
            }
        }
        __syncthreads();

        // ea GEMM: K=64 -> 4 k16 planes
        float acc[4][8][4];
        #pragma unroll
        for (int mt = 0; mt < 4; mt++)
            #pragma unroll
            for (int nt = 0; nt < 8; nt++)
                #pragma unroll
                for (int i = 0; i < 4; i++) acc[mt][nt][i] = 0.f;

        #pragma unroll
        for (int ks = 0; ks < 4; ks++) {
            const uint32_t* Aks = AEA + ks * 1024;
            const uint32_t* Bks = WC + ks * 2048;
            const int qz = q2 ^ zn ^ ((ks & 1) << 1);
            uint32_t af[4][4];
            #pragma unroll
            for (int mt = 0; mt < 4; mt++) {
                const int r0 = rbase + 16 * mt;
                uint2 lo = *(const uint2*)&Aks[r0 * 8 + qz];
                uint2 hi = *(const uint2*)&Aks[(r0 + 8) * 8 + qz];
                af[mt][0] = lo.x; af[mt][1] = hi.x;
                af[mt][2] = lo.y; af[mt][3] = hi.y;
            }
            #pragma unroll
            for (int nt = 0; nt < 8; nt++) {
                const int n = 64 * wc + 8 * nt + gq;
                uint2 bv = *(const uint2*)&Bks[n * 8 + qz];
                #pragma unroll
                for (int mt = 0; mt < 4; mt++) mma16(acc[mt][nt], af[mt], bv.x, bv.y);
            }
        }

        // epilogue: h = relu(acc + uv); scatter (sorted dests -> L2-local)
        #pragma unroll
        for (int mt = 0; mt < 4; mt++) {
            const int r0 = rbase + 16 * mt;
            const uint32_t* uv0 = UV + r0 * 136 + hh68;
            const uint32_t* uv1 = UV + (r0 + 8) * 136 + hh68;
            float* hs0 = g_hsum + (size_t)rows_s[r0] * 256;
            float* hs1 = g_hsum + (size_t)rows_s[r0 + 8] * 256;
            #pragma unroll
            for (int nt = 0; nt < 8; nt++) {
                const int off = (wbase + 4 * nt) ^ g4;
                const int cn  = 64 * wc + 8 * nt + 2 * (lane & 3);
                float2 f0 = __half22float2(*(const __half2*)&uv0[off]);
                float2 f1 = __half22float2(*(const __half2*)&uv1[off]);
                red2(hs0 + cn, fmaxf(acc[mt][nt][0] + f0.x, 0.f),
                               fmaxf(acc[mt][nt][1] + f0.y, 0.f));
                red2(hs1 + cn, fmaxf(acc[mt][nt][2] + f1.x, 0.f),
                               fmaxf(acc[mt][nt][3] + f1.y, 0.f));
            }
        }
    }
}

// ============================================================================
// g2: out[n,:] = fp16(hsum[n]) @ W2 + degf[n]*b2  (unchanged)
// ============================================================================
__global__ void __launch_bounds__(256, 1)
edgeconv_g2(const float* __restrict__ b2, float* __restrict__ out) {
    extern __shared__ char smem[];
    const int tid  = threadIdx.x;
    const int wid  = tid >> 5;
    const int lane = tid & 31;
    const int wr   = wid >> 1;
    const int wc   = wid & 1;
    const int gq   = lane >> 2;
    const int q2   = 2 * (lane & 3);
    const int zn   = gq & 4;

    float* sB2 = (float*)(smem + F_B2_OFF);
    if (tid < 128) sB2[tid] = b2[tid];
    {
        const float4* src = (const float4*)g_W2h;
        float4* dst = (float4*)(smem + F_W2_OFF);
        #pragma unroll
        for (int i = 0; i < 16; i++) dst[tid + i * 256] = src[tid + i * 256];
    }
    __syncthreads();

    float2 b2v[8];
    #pragma unroll
    for (int nt = 0; nt < 8; nt++)
        b2v[nt] = *(const float2*)&sB2[64 * wc + 8 * nt + 2 * (lane & 3)];

    const int rbase = 32 * wr + gq;
    const int e     = tid >> 1;
    const int half  = tid & 1;

    for (int tile = blockIdx.x; tile < N_TILES2; tile += GRID_MAIN) {
        const int rg = tile * 128 + e;
        const bool ok = rg < NN_NODES;
        float4 v[4];
        {
            const float* p = g_hsum + (size_t)rg * 256 + half * 16;
            #pragma unroll
            for (int j = 0; j < 4; j++)
                v[j] = ok ? *(const float4*)(p + j * 4) : make_float4(0, 0, 0, 0);
            stage_row((uint32_t*)(smem + F_ABUF_OFF), e, half, 1024, v);
            p = g_hsum + (size_t)rg * 256 + 32 + half * 16;
            #pragma unroll
            for (int j = 0; j < 4; j++)
                v[j] = ok ? *(const float4*)(p + j * 4) : make_float4(0, 0, 0, 0);
        }
        __syncthreads();

        float acc[2][8][4];
        #pragma unroll
        for (int mt = 0; mt < 2; mt++)
            #pragma unroll
            for (int nt = 0; nt < 8; nt++)
                #pragma unroll
                for (int i = 0; i < 4; i++) acc[mt][nt][i] = 0.f;

        #pragma unroll 1
        for (int j = 0; j < 8; j++) {
            const int s = j & 1;
            const uint32_t* A16 = (const uint32_t*)(smem + F_ABUF_OFF + s * 8192);
            const uint32_t* B16 = (const uint32_t*)(smem + F_W2_OFF + j * 8192);
            #pragma unroll
            for (int ks = 0; ks < 2; ks++) {
                const uint32_t* Aks = A16 + ks * 1024;
                const uint32_t* Bks = B16 + ks * 1024;
                const int qz = q2 ^ zn ^ (ks << 1);
                uint32_t af[2][4];
                #pragma unroll
                for (int mt = 0; mt < 2; mt++) {
                    const int r0 = rbase + 16 * mt;
                    uint2 lo = *(const uint2*)&Aks[r0 * 8 + qz];
                    uint2 hi = *(const uint2*)&Aks[(r0 + 8) * 8 + qz];
                    af[mt][0] = lo.x; af[mt][1] = hi.x;
                    af[mt][2] = lo.y; af[mt][3] = hi.y;
                }
                #pragma unroll
                for (int nt = 0; nt < 8; nt++) {
                    const int n = 64 * wc + 8 * nt + gq;
                    uint2 bv = *(const uint2*)&Bks[n * 8 + qz];
                    #pragma unroll
                    for (int mt = 0; mt < 2; mt++) mma16(acc[mt][nt], af[mt], bv.x, bv.y);
                }
            }
            if (j < 7) {
                stage_row((uint32_t*)(smem + F_ABUF_OFF + (s ^ 1) * 8192), e, half, 1024, v);
                if (j < 6) {
                    const float* p = g_hsum + (size_t)rg * 256 + (j + 2) * 32 + half * 16;
                    #pragma unroll
                    for (int jj = 0; jj < 4; jj++)
                        v[jj] = ok ? *(const float4*)(p + jj * 4) : make_float4(0, 0, 0, 0);
                }
            }
            __syncthreads();
        }

        #pragma unroll
        for (int mt = 0; mt < 2; mt++) {
            const int r0 = tile * 128 + rbase + 16 * mt;
            const bool ok0 = r0 < NN_NODES;
            const bool ok1 = (r0 + 8) < NN_NODES;
            const float dg0 = ok0 ? g_degf[r0] : 0.f;
            const float dg1 = ok1 ? g_degf[r0 + 8] : 0.f;
            #pragma unroll
            for (int nt = 0; nt < 8; nt++) {
                const int cn = 64 * wc + 8 * nt + 2 * (lane & 3);
                if (ok0) {
                    float2 o = make_float2(acc[mt][nt][0] + dg0 * b2v[nt].x,
                                           acc[mt][nt][1] + dg0 * b2v[nt].y);
                    *(float2*)(out + (size_t)r0 * 128 + cn) = o;
                }
                if (ok1) {
                    float2 o = make_float2(acc[mt][nt][2] + dg1 * b2v[nt].x,
                                           acc[mt][nt][3] + dg1 * b2v[nt].y);
                    *(float2*)(out + (size_t)(r0 + 8) * 128 + cn) = o;
                }
            }
        }
    }
}

// ============================================================================
// Launch
// ============================================================================
extern "C" void kernel_launch(void* const* d_in, const int* in_sizes, int n_in,
                              void* d_out, int out_size) {
    const float* x  = (const float*)d_in[0];
    const void*  ei = d_in[1];
    const float* ea = (const float*)d_in[2];
    const float* W1 = (const float*)d_in[3];
    const float* b1 = (const float*)d_in[4];
    const float* W2 = (const float*)d_in[5];
    const float* b2 = (const float*)d_in[6];
    float* out = (float*)d_out;

    cudaFuncSetAttribute(edgeconv_g0,
                         cudaFuncAttributeMaxDynamicSharedMemorySize, SMEM_G0);
    cudaFuncSetAttribute(edgeconv_g1,
                         cudaFuncAttributeMaxDynamicSharedMemorySize, SMEM_G1);
    cudaFuncSetAttribute(edgeconv_g2,
                         cudaFuncAttributeMaxDynamicSharedMemorySize, SMEM_FIN);

    setup_kernel<<<SETUP_BLOCKS, 256>>>(ei, W1, W2);
    hist_kernel<<<(E_TOTAL + 255) / 256, 256>>>(ei);
    scan1_kernel<<<NCHUNKS, 1024>>>();
    scan2_kernel<<<1, 32>>>();
    scan3_kernel<<<(NN_NODES + 255) / 256, 256>>>();
    place_kernel<<<(E_TOTAL + 255) / 256, 256>>>(ei);
    edgeconv_g0<<<GRID_MAIN, 256, SMEM_G0>>>(x, b1);
    edgeconv_g1<<<GRID_MAIN, 256, SMEM_G1>>>(ea);
    edgeconv_g2<<<GRID_MAIN, 256, SMEM_FIN>>>(b2, out);
}

// round 15
// speedup vs baseline: 1.2158x; 1.0773x over previous
#include <cuda_runtime.h>
#include <cuda_fp16.h>
#include <stdint.h>

// ============================================================================
//   h_e = relu(x[row]@W1a + x[col]@W1b + ea@W1c + b1)
//   g0: u = x@W1a + b1, v = x@W1b (dense per node, fp16)
//   g1: dest-sorted edges; h = relu(u[row]+v[col]+ea@W1c) staged fp16 in UV;
//       same-dest runs aggregated in-register -> ~6.4x fewer RED ops
//   g2: out[n] = hsum[n]@W2 + degf[n]*b2
// fp16 mma.sync.m16n8k16, f32 accumulate.
// ============================================================================
#define E_TOTAL   640000
#define NN_NODES  100000
#define OUT_ELEMS (NN_NODES * 128)
#define TILE_E    128
#define N_TILES   (E_TOTAL / TILE_E)   // 5000
#define GRID_MAIN 148
#define N_TILES0  1563                 // ceil(100000/64)
#define N_TILES2  782                  // ceil(100000/128)
#define NCHUNKS   98                   // ceil(100000/1024) scan chunks

// g0 SMEM
#define G0_A    0        // [8 planes][64 rows][8 words] = 16384 B
#define G0_WA   16384    // 65536 B
#define G0_WB   81920    // 65536 B
#define G0_B1   147456   // 256 floats
#define SMEM_G0 148480

// g1 SMEM
#define G1_ROWS 0        // 128 int
#define G1_COLS 512      // 128 int
#define G1_EIDX 1024     // 128 int
#define G1_WC   1536     // [4][256][8] words = 32768 B
#define G1_AEA  34304    // [4][128][8] words = 16384 B
#define G1_UV   50688    // 128 rows x 136 words x 4 B = 69632 B
#define SMEM_G1 120320

// g2 SMEM
#define F_B2_OFF   0
#define F_ABUF_OFF 1024  // 2 x 8192
#define F_W2_OFF   17408 // 65536
#define SMEM_FIN   82944

// ============================================================================
// Device scratch (allocation-free)
// ============================================================================
__device__ __align__(16) __half g_Wa[8 * 2048 * 2];
__device__ __align__(16) __half g_Wb[8 * 2048 * 2];
__device__ __align__(16) __half g_Wc[4 * 2048 * 2];
__device__ __align__(16) __half g_W2h[8 * 4096];
__device__ __align__(16) __half g_u[NN_NODES * 256];
__device__ __align__(16) __half g_v[NN_NODES * 256];
__device__ __align__(16) float  g_hsum[NN_NODES * 256];
__device__ float g_degf[NN_NODES];
__device__ int   g_is64;
// counting-sort scratch
__device__ int g_cnt[NN_NODES];
__device__ int g_off[NN_NODES];
__device__ int g_blksum[NCHUNKS];
__device__ int g_rows_srt[E_TOTAL];
__device__ int g_cols_srt[E_TOTAL];
__device__ int g_eidx_srt[E_TOTAL];

// ============================================================================
// Helpers
// ============================================================================
__device__ __forceinline__ uint32_t f2h2(float lo, float hi) {
    uint32_t r;
    asm("cvt.rn.f16x2.f32 %0, %1, %2;" : "=r"(r) : "f"(hi), "f"(lo));
    return r;
}
__device__ __forceinline__ uint32_t hadd2u(uint32_t a, uint32_t b) {
    uint32_t r;
    asm("add.rn.f16x2 %0, %1, %2;" : "=r"(r) : "r"(a), "r"(b));
    return r;
}
__device__ __forceinline__ void mma16(float* d, const uint32_t* a,
                                      uint32_t b0, uint32_t b1) {
    asm volatile(
        "mma.sync.aligned.m16n8k16.row.col.f32.f16.f16.f32 "
        "{%0,%1,%2,%3}, {%4,%5,%6,%7}, {%8,%9}, {%0,%1,%2,%3};"
        : "+f"(d[0]), "+f"(d[1]), "+f"(d[2]), "+f"(d[3])
        : "r"(a[0]), "r"(a[1]), "r"(a[2]), "r"(a[3]), "r"(b0), "r"(b1));
}
__device__ __forceinline__ void red2(float* p, float v0, float v1) {
    asm volatile("red.global.add.v2.f32 [%0], {%1, %2};"
                 :: "l"(p), "f"(v0), "f"(v1) : "memory");
}
__device__ __forceinline__ int ld_idx(const void* ei, int pos) {
    return g_is64 ? (int)((const long long*)ei)[pos] : ((const int*)ei)[pos];
}

// Stage 16 consecutive k-values (one k16 plane) of one row into an operand
// image. word = ks*stride + row*8 + ((2s)^z) + hi, z = (row&4) ^ ((ks&1)<<1).
__device__ __forceinline__ void stage_row(uint32_t* ab, int row, int ks,
                                          int stride, const float4* v) {
    uint32_t* rp = ab + ks * stride + row * 8;
    const int z = (row & 4) ^ ((ks & 1) << 1);
    *(uint2*)&rp[0 ^ z] = make_uint2(f2h2(v[0].x, v[0].y), f2h2(v[2].x, v[2].y));
    *(uint2*)&rp[2 ^ z] = make_uint2(f2h2(v[0].z, v[0].w), f2h2(v[2].z, v[2].w));
    *(uint2*)&rp[4 ^ z] = make_uint2(f2h2(v[1].x, v[1].y), f2h2(v[3].x, v[3].y));
    *(uint2*)&rp[6 ^ z] = make_uint2(f2h2(v[1].z, v[1].w), f2h2(v[3].z, v[3].w));
}

// Matching weight-image element store (setup side).
__device__ __forceinline__ void img_store(__half* img, int kk, int n,
                                          int plane_words, float val) {
    const int ks = kk >> 4, w = (kk & 15) >> 1;
    const int z = (n & 4) ^ ((ks & 1) << 1);
    const int word = ks * plane_words + n * 8 + ((2 * (w & 3)) ^ z) + (w >> 2);
    img[word * 2 + (kk & 1)] = __float2half_rn(val);
}

// ============================================================================
// Setup + counting sort
// ============================================================================
#define SETUP_BLOCKS 25840
__global__ void setup_kernel(const void* ei, const float* __restrict__ W1,
                             const float* __restrict__ W2) {
    int i = blockIdx.x * 256 + threadIdx.x;
    if (i < 6400000) {
        ((float4*)g_hsum)[i] = make_float4(0.f, 0.f, 0.f, 0.f);
        return;
    }
    i -= 6400000;
    if (i < NN_NODES) { g_cnt[i] = 0; return; }
    i -= NN_NODES;
    if (i < 32768) {                       // W1a
        int kk = i >> 8, n = i & 255;
        img_store(g_Wa, kk, n, 2048, W1[kk * 256 + n]);
    } else if (i < 65536) {                // W1b
        int j = i - 32768;
        int kk = j >> 8, n = j & 255;
        img_store(g_Wb, kk, n, 2048, W1[(kk + 128) * 256 + n]);
    } else if (i < 81920) {                // W1c
        int j = i - 65536;
        int kk = j >> 8, n = j & 255;
        img_store(g_Wc, kk, n, 2048, W1[(kk + 256) * 256 + n]);
    } else if (i < 114688) {               // W2
        int j = i - 81920;
        int k = j >> 7, n = j & 127;
        img_store(g_W2h + (k >> 5) * 4096, k & 31, n, 1024, W2[k * 128 + n]);
    } else if (i == 114688) {              // int64 probe
        const unsigned* w = (const unsigned*)ei;
        int is64 = 1;
        for (int t = 0; t < 64; t++)
            if (w[2 * t + 1] != 0) { is64 = 0; break; }
        g_is64 = is64;
    }
}

__global__ void hist_kernel(const void* ei) {
    int e = blockIdx.x * 256 + threadIdx.x;
    if (e < E_TOTAL) atomicAdd(&g_cnt[ld_idx(ei, e)], 1);
}

__global__ void scan1_kernel() {
    __shared__ int s[1024];
    int g = blockIdx.x * 1024 + threadIdx.x;
    int v = (g < NN_NODES) ? g_cnt[g] : 0;
    s[threadIdx.x] = v;
    __syncthreads();
    #pragma unroll
    for (int d = 1; d < 1024; d <<= 1) {
        int t = (threadIdx.x >= d) ? s[threadIdx.x - d] : 0;
        __syncthreads();
        s[threadIdx.x] += t;
        __syncthreads();
    }
    if (g < NN_NODES) {
        g_off[g] = s[threadIdx.x] - v;
        g_degf[g] = (float)v;
    }
    if (threadIdx.x == 1023) g_blksum[blockIdx.x] = s[1023];
}

__global__ void scan2_kernel() {
    if (threadIdx.x == 0) {
        int acc = 0;
        for (int i = 0; i < NCHUNKS; i++) {
            int t = g_blksum[i];
            g_blksum[i] = acc;
            acc += t;
        }
    }
}

__global__ void scan3_kernel() {
    int g = blockIdx.x * 256 + threadIdx.x;
    if (g < NN_NODES) {
        int o = g_off[g] + g_blksum[g >> 10];
        g_off[g] = o;
        g_cnt[g] = o;
    }
}

__global__ void place_kernel(const void* ei) {
    int e = blockIdx.x * 256 + threadIdx.x;
    if (e < E_TOTAL) {
        int r = ld_idx(ei, e);
        int c = ld_idx(ei, E_TOTAL + e);
        int pos = atomicAdd(&g_cnt[r], 1);
        g_rows_srt[pos] = r;
        g_cols_srt[pos] = c;
        g_eidx_srt[pos] = e;
    }
}

// ============================================================================
// g0: u[n] = fp16(x[n]@W1a + b1), v[n] = fp16(x[n]@W1b).  (unchanged)
// ============================================================================
__global__ void __launch_bounds__(256, 1)
edgeconv_g0(const float* __restrict__ x, const float* __restrict__ b1) {
    extern __shared__ char smem[];
    const int tid  = threadIdx.x;
    const int wid  = tid >> 5;
    const int lane = tid & 31;
    const int gq   = lane >> 2;
    const int q2   = 2 * (lane & 3);
    const int zn   = gq & 4;
    const int rowg = wid & 1;
    const int colh = (wid >> 1) & 1;
    const int outs = wid >> 2;

    {
        const float4* sa = (const float4*)g_Wa;
        const float4* sb = (const float4*)g_Wb;
        float4* da = (float4*)(smem + G0_WA);
        float4* db = (float4*)(smem + G0_WB);
        #pragma unroll
        for (int i = 0; i < 16; i++) {
            da[tid + i * 256] = sa[tid + i * 256];
            db[tid + i * 256] = sb[tid + i * 256];
        }
        ((float*)(smem + G0_B1))[tid] = b1[tid];
    }
    __syncthreads();

    float2 b1v[16];
    #pragma unroll
    for (int nt = 0; nt < 16; nt++)
        b1v[nt] = *(const float2*)((float*)(smem + G0_B1) +
                                   128 * colh + 8 * nt + 2 * (lane & 3));

    const int rbase = 32 * rowg + gq;
    const int e   = tid >> 2;
    const int sub = tid & 3;
    uint32_t* Axw = (uint32_t*)(smem + G0_A);
    const uint32_t* Wim = (const uint32_t*)(smem + (outs ? G0_WB : G0_WA));

    for (int tile = blockIdx.x; tile < N_TILES0; tile += GRID_MAIN) {
        const int grow = tile * 64 + e;
        const bool gok = grow < NN_NODES;
        __syncthreads();
        #pragma unroll
        for (int pi = 0; pi < 2; pi++) {
            const int p = 2 * sub + pi;
            float4 v[4];
            const float* sp = x + (size_t)grow * 128 + p * 16;
            #pragma unroll
            for (int j = 0; j < 4; j++)
                v[j] = gok ? *(const float4*)(sp + j * 4) : make_float4(0, 0, 0, 0);
            stage_row(Axw, e, p, 512, v);
        }
        __syncthreads();

        float acc[2][16][4];
        #pragma unroll
        for (int mt = 0; mt < 2; mt++)
            #pragma unroll
            for (int nt = 0; nt < 16; nt++) {
                float bx = outs ? 0.f : b1v[nt].x;
                float by = outs ? 0.f : b1v[nt].y;
                acc[mt][nt][0] = bx; acc[mt][nt][1] = by;
                acc[mt][nt][2] = bx; acc[mt][nt][3] = by;
            }

        #pragma unroll
        for (int ks = 0; ks < 8; ks++) {
            const uint32_t* Aks = Axw + ks * 512;
            const uint32_t* Bks = Wim + ks * 2048;
            const int qz = q2 ^ zn ^ ((ks & 1) << 1);
            uint32_t af[2][4];
            #pragma unroll
            for (int mt = 0; mt < 2; mt++) {
                const int r0 = rbase + 16 * mt;
                uint2 lo = *(const uint2*)&Aks[r0 * 8 + qz];
                uint2 hi = *(const uint2*)&Aks[(r0 + 8) * 8 + qz];
                af[mt][0] = lo.x; af[mt][1] = hi.x;
                af[mt][2] = lo.y; af[mt][3] = hi.y;
            }
            #pragma unroll
            for (int nt = 0; nt < 16; nt++) {
                const int n = 128 * colh + 8 * nt + gq;
                uint2 bv = *(const uint2*)&Bks[n * 8 + qz];
                #pragma unroll
                for (int mt = 0; mt < 2; mt++) mma16(acc[mt][nt], af[mt], bv.x, bv.y);
            }
        }

        __half* outp = outs ? g_v : g_u;
        #pragma unroll
        for (int mt = 0; mt < 2; mt++) {
            const int r0 = tile * 64 + rbase + 16 * mt;
            #pragma unroll
            for (int nt = 0; nt < 16; nt++) {
                const int cn = 128 * colh + 8 * nt + 2 * (lane & 3);
                if (r0 < NN_NODES)
                    *(uint32_t*)(outp + (size_t)r0 * 256 + cn) =
                        f2h2(acc[mt][nt][0], acc[mt][nt][1]);
                if (r0 + 8 < NN_NODES)
                    *(uint32_t*)(outp + (size_t)(r0 + 8) * 256 + cn) =
                        f2h2(acc[mt][nt][2], acc[mt][nt][3]);
            }
        }
    }
}

// ============================================================================
// g1: dest-sorted edges; ea@W1c GEMM; h -> fp16 in-place in UV; run-aggregated
//     scatter. UV gather word 4j+m of half hh <-> cols 128hh + 8(j^e2) + 2m.
// ============================================================================
__global__ void __launch_bounds__(256, 1)
edgeconv_g1(const float* __restrict__ ea) {
    extern __shared__ char smem[];
    const int tid  = threadIdx.x;
    const int wid  = tid >> 5;
    const int lane = tid & 31;
    const int gq   = lane >> 2;
    const int q2   = 2 * (lane & 3);
    const int zn   = gq & 4;
    const int wr   = wid >> 2;   // rows [64wr, +64)
    const int wc   = wid & 3;    // cols [64wc, +64)

    int* rows_s = (int*)(smem + G1_ROWS);
    int* cols_s = (int*)(smem + G1_COLS);
    int* eidx_s = (int*)(smem + G1_EIDX);
    uint32_t* WC  = (uint32_t*)(smem + G1_WC);
    uint32_t* AEA = (uint32_t*)(smem + G1_AEA);
    uint32_t* UV  = (uint32_t*)(smem + G1_UV);

    {   // resident W1c image (32 KB)
        const float4* src = (const float4*)g_Wc;
        float4* dst = (float4*)(smem + G1_WC);
        #pragma unroll
        for (int i = 0; i < 8; i++) dst[tid + i * 256] = src[tid + i * 256];
    }

    const int rbase = 64 * wr + gq;
    const int e  = tid >> 1;
    const int h  = tid & 1;
    const int e2 = (e >> 2) & 1;
    const int hh68 = 68 * (wc >> 1);
    const int wbase = 32 * (wc & 1) + (lane & 3);
    const int g4 = gq & 4;
    const int m_  = lane & 3;     // scatter lane roles
    const int jlA = lane >> 2;

    for (int tile = blockIdx.x; tile < N_TILES; tile += GRID_MAIN) {
        const int ebase = tile * TILE_E;
        __syncthreads();   // prior tile scatter done with UV / indices
        if (tid < 128) {
            rows_s[tid] = g_rows_srt[ebase + tid];
            cols_s[tid] = g_cols_srt[ebase + tid];
            eidx_s[tid] = g_eidx_srt[ebase + tid];
        }
        __syncthreads();

        // stage ea chunk via sorted edge index
        #pragma unroll
        for (int pi = 0; pi < 2; pi++) {
            const int p = 2 * h + pi;
            float4 v[4];
            const float* sp = ea + (size_t)eidx_s[e] * 64 + p * 16;
            #pragma unroll
            for (int j = 0; j < 4; j++) v[j] = *(const float4*)(sp + j * 4);
            stage_row(AEA, e, p, 1024, v);
        }
        // stage uv = u[row]+v[col]
        {
            const __half* up = g_u + (size_t)rows_s[e] * 256;
            const __half* vp = g_v + (size_t)cols_s[e] * 256;
            uint32_t* uvrow = UV + e * 136 + 68 * h;
            #pragma unroll
            for (int j = 0; j < 16; j++) {
                const int lg = 16 * h + (j ^ e2);
                uint4 a = *(const uint4*)(up + lg * 8);
                uint4 b = *(const uint4*)(vp + lg * 8);
                uint4 r;
                r.x = hadd2u(a.x, b.x); r.y = hadd2u(a.y, b.y);
                r.z = hadd2u(a.z, b.z); r.w = hadd2u(a.w, b.w);
                *(uint4*)(uvrow + 4 * j) = r;
            }
        }
        __syncthreads();

        // ea GEMM: K=64 -> 4 k16 planes
        float acc[4][8][4];
        #pragma unroll
        for (int mt = 0; mt < 4; mt++)
            #pragma unroll
            for (int nt = 0; nt < 8; nt++)
                #pragma unroll
                for (int i = 0; i < 4; i++) acc[mt][nt][i] = 0.f;

        #pragma unroll
        for (int ks = 0; ks < 4; ks++) {
            const uint32_t* Aks = AEA + ks * 1024;
            const uint32_t* Bks = WC + ks * 2048;
            const int qz = q2 ^ zn ^ ((ks & 1) << 1);
            uint32_t af[4][4];
            #pragma unroll
            for (int mt = 0; mt < 4; mt++) {
                const int r0 = rbase + 16 * mt;
                uint2 lo = *(const uint2*)&Aks[r0 * 8 + qz];
                uint2 hi = *(const uint2*)&Aks[(r0 + 8) * 8 + qz];
                af[mt][0] = lo.x; af[mt][1] = hi.x;
                af[mt][2] = lo.y; af[mt][3] = hi.y;
            }
            #pragma unroll
            for (int nt = 0; nt < 8; nt++) {
                const int n = 64 * wc + 8 * nt + gq;
                uint2 bv = *(const uint2*)&Bks[n * 8 + qz];
                #pragma unroll
                for (int mt = 0; mt < 4; mt++) mma16(acc[mt][nt], af[mt], bv.x, bv.y);
            }
        }

        // epilogue: h = relu(acc + uv) -> fp16 back in place (single-owner)
        #pragma unroll
        for (int mt = 0; mt < 4; mt++) {
            const int r0 = rbase + 16 * mt;
            uint32_t* uv0 = UV + r0 * 136 + hh68;
            uint32_t* uv1 = UV + (r0 + 8) * 136 + hh68;
            #pragma unroll
            for (int nt = 0; nt < 8; nt++) {
                const int off = (wbase + 4 * nt) ^ g4;
                float2 f0 = __half22float2(*(const __half2*)&uv0[off]);
                float2 f1 = __half22float2(*(const __half2*)&uv1[off]);
                uv0[off] = f2h2(fmaxf(acc[mt][nt][0] + f0.x, 0.f),
                                fmaxf(acc[mt][nt][1] + f0.y, 0.f));
                uv1[off] = f2h2(fmaxf(acc[mt][nt][2] + f1.x, 0.f),
                                fmaxf(acc[mt][nt][3] + f1.y, 0.f));
            }
        }
        __syncthreads();

        // aggregated scatter: warp-per-row; one RED set per same-dest run
        #pragma unroll 1
        for (int t16 = 0; t16 < 16; t16++) {
            const int r = 16 * wid + t16;
            const int dest = rows_s[r];
            if (r > 0 && rows_s[r - 1] == dest) continue;  // warp-uniform
            float2 s[4];
            #pragma unroll
            for (int t = 0; t < 4; t++) s[t] = make_float2(0.f, 0.f);
            int rr = r;
            do {
                const int e2r = (rr >> 2) & 1;
                const uint32_t* rowp = UV + rr * 136;
                #pragma unroll
                for (int t = 0; t < 4; t++) {
                    const int h_ = t & 1;
                    const int jl = jlA + 8 * (t >> 1);
                    const int w  = 4 * (jl ^ e2r) + m_;
                    float2 f = __half22float2(*(const __half2*)&rowp[68 * h_ + w]);
                    s[t].x += f.x; s[t].y += f.y;
                }
                rr++;
            } while (rr < 128 && rows_s[rr] == dest);
            float* dst = g_hsum + (size_t)dest * 256;
            #pragma unroll
            for (int t = 0; t < 4; t++) {
                const int h_ = t & 1;
                const int jl = jlA + 8 * (t >> 1);
                red2(dst + 128 * h_ + 8 * jl + 2 * m_, s[t].x, s[t].y);
            }
        }
    }
}

// ============================================================================
// g2: out[n,:] = fp16(hsum[n]) @ W2 + degf[n]*b2  (unchanged)
// ============================================================================
__global__ void __launch_bounds__(256, 1)
edgeconv_g2(const float* __restrict__ b2, float* __restrict__ out) {
    extern __shared__ char smem[];
    const int tid  = threadIdx.x;
    const int wid  = tid >> 5;
    const int lane = tid & 31;
    const int wr   = wid >> 1;
    const int wc   = wid & 1;
    const int gq   = lane >> 2;
    const int q2   = 2 * (lane & 3);
    const int zn   = gq & 4;

    float* sB2 = (float*)(smem + F_B2_OFF);
    if (tid < 128) sB2[tid] = b2[tid];
    {
        const float4* src = (const float4*)g_W2h;
        float4* dst = (float4*)(smem + F_W2_OFF);
        #pragma unroll
        for (int i = 0; i < 16; i++) dst[tid + i * 256] = src[tid + i * 256];
    }
    __syncthreads();

    float2 b2v[8];
    #pragma unroll
    for (int nt = 0; nt < 8; nt++)
        b2v[nt] = *(const float2*)&sB2[64 * wc + 8 * nt + 2 * (lane & 3)];

    const int rbase = 32 * wr + gq;
    const int e     = tid >> 1;
    const int half  = tid & 1;

    for (int tile = blockIdx.x; tile < N_TILES2; tile += GRID_MAIN) {
        const int rg = tile * 128 + e;
        const bool ok = rg < NN_NODES;
        float4 v[4];
        {
            const float* p = g_hsum + (size_t)rg * 256 + half * 16;
            #pragma unroll
            for (int j = 0; j < 4; j++)
                v[j] = ok ? *(const float4*)(p + j * 4) : make_float4(0, 0, 0, 0);
            stage_row((uint32_t*)(smem + F_ABUF_OFF), e, half, 1024, v);
            p = g_hsum + (size_t)rg * 256 + 32 + half * 16;
            #pragma unroll
            for (int j = 0; j < 4; j++)
                v[j] = ok ? *(const float4*)(p + j * 4) : make_float4(0, 0, 0, 0);
        }
        __syncthreads();

        float acc[2][8][4];
        #pragma unroll
        for (int mt = 0; mt < 2; mt++)
            #pragma unroll
            for (int nt = 0; nt < 8; nt++)
                #pragma unroll
                for (int i = 0; i < 4; i++) acc[mt][nt][i] = 0.f;

        #pragma unroll 1
        for (int j = 0; j < 8; j++) {
            const int s = j & 1;
            const uint32_t* A16 = (const uint32_t*)(smem + F_ABUF_OFF + s * 8192);
            const uint32_t* B16 = (const uint32_t*)(smem + F_W2_OFF + j * 8192);
            #pragma unroll
            for (int ks = 0; ks < 2; ks++) {
                const uint32_t* Aks = A16 + ks * 1024;
                const uint32_t* Bks = B16 + ks * 1024;
                const int qz = q2 ^ zn ^ (ks << 1);
                uint32_t af[2][4];
                #pragma unroll
                for (int mt = 0; mt < 2; mt++) {
                    const int r0 = rbase + 16 * mt;
                    uint2 lo = *(const uint2*)&Aks[r0 * 8 + qz];
                    uint2 hi = *(const uint2*)&Aks[(r0 + 8) * 8 + qz];
                    af[mt][0] = lo.x; af[mt][1] = hi.x;
                    af[mt][2] = lo.y; af[mt][3] = hi.y;
                }
                #pragma unroll
                for (int nt = 0; nt < 8; nt++) {
                    const int n = 64 * wc + 8 * nt + gq;
                    uint2 bv = *(const uint2*)&Bks[n * 8 + qz];
                    #pragma unroll
                    for (int mt = 0; mt < 2; mt++) mma16(acc[mt][nt], af[mt], bv.x, bv.y);
                }
            }
            if (j < 7) {
                stage_row((uint32_t*)(smem + F_ABUF_OFF + (s ^ 1) * 8192), e, half, 1024, v);
                if (j < 6) {
                    const float* p = g_hsum + (size_t)rg * 256 + (j + 2) * 32 + half * 16;
                    #pragma unroll
                    for (int jj = 0; jj < 4; jj++)
                        v[jj] = ok ? *(const float4*)(p + jj * 4) : make_float4(0, 0, 0, 0);
                }
            }
            __syncthreads();
        }

        #pragma unroll
        for (int mt = 0; mt < 2; mt++) {
            const int r0 = tile * 128 + rbase + 16 * mt;
            const bool ok0 = r0 < NN_NODES;
            const bool ok1 = (r0 + 8) < NN_NODES;
            const float dg0 = ok0 ? g_degf[r0] : 0.f;
            const float dg1 = ok1 ? g_degf[r0 + 8] : 0.f;
            #pragma unroll
            for (int nt = 0; nt < 8; nt++) {
                const int cn = 64 * wc + 8 * nt + 2 * (lane & 3);
                if (ok0) {
                    float2 o = make_float2(acc[mt][nt][0] + dg0 * b2v[nt].x,
                                           acc[mt][nt][1] + dg0 * b2v[nt].y);
                    *(float2*)(out + (size_t)r0 * 128 + cn) = o;
                }
                if (ok1) {
                    float2 o = make_float2(acc[mt][nt][2] + dg1 * b2v[nt].x,
                                           acc[mt][nt][3] + dg1 * b2v[nt].y);
                    *(float2*)(out + (size_t)(r0 + 8) * 128 + cn) = o;
                }
            }
        }
    }
}

// ============================================================================
// Launch
// ============================================================================
extern "C" void kernel_launch(void* const* d_in, const int* in_sizes, int n_in,
                              void* d_out, int out_size) {
    const float* x  = (const float*)d_in[0];
    const void*  ei = d_in[1];
    const float* ea = (const float*)d_in[2];
    const float* W1 = (const float*)d_in[3];
    const float* b1 = (const float*)d_in[4];
    const float* W2 = (const float*)d_in[5];
    const float* b2 = (const float*)d_in[6];
    float* out = (float*)d_out;

    cudaFuncSetAttribute(edgeconv_g0,
                         cudaFuncAttributeMaxDynamicSharedMemorySize, SMEM_G0);
    cudaFuncSetAttribute(edgeconv_g1,
                         cudaFuncAttributeMaxDynamicSharedMemorySize, SMEM_G1);
    cudaFuncSetAttribute(edgeconv_g2,
                         cudaFuncAttributeMaxDynamicSharedMemorySize, SMEM_FIN);

    setup_kernel<<<SETUP_BLOCKS, 256>>>(ei, W1, W2);
    hist_kernel<<<(E_TOTAL + 255) / 256, 256>>>(ei);
    scan1_kernel<<<NCHUNKS, 1024>>>();
    scan2_kernel<<<1, 32>>>();
    scan3_kernel<<<(NN_NODES + 255) / 256, 256>>>();
    place_kernel<<<(E_TOTAL + 255) / 256, 256>>>(ei);
    edgeconv_g0<<<GRID_MAIN, 256, SMEM_G0>>>(x, b1);
    edgeconv_g1<<<GRID_MAIN, 256, SMEM_G1>>>(ea);
    edgeconv_g2<<<GRID_MAIN, 256, SMEM_FIN>>>(b2, out);
}

// round 17
// speedup vs baseline: 1.2429x; 1.0223x over previous
#include <cuda_runtime.h>
#include <cuda_fp16.h>
#include <stdint.h>

// ============================================================================
//   h_e = relu(x[row]@W1a + x[col]@W1b + ea@W1c + b1)
//   g0: u = x@W1a + b1, v = x@W1b (dense per node, fp16)
//   g1: dest-sorted edges; h = relu(u[row]+v[col]+ea@W1c) staged fp16 in UV;
//       same-dest runs aggregated in f32 regs -> fp16 RED into hsum (fp16)
//   g2: out[n] = hsum[n]@W2 + degf[n]*b2
// fp16 mma.sync.m16n8k16, f32 accumulate.
// ============================================================================
#define E_TOTAL   640000
#define NN_NODES  100000
#define OUT_ELEMS (NN_NODES * 128)
#define TILE_E    128
#define N_TILES   (E_TOTAL / TILE_E)   // 5000
#define GRID_MAIN 148
#define N_TILES0  1563                 // ceil(100000/64)
#define N_TILES2  782                  // ceil(100000/128)
#define NCHUNKS   98                   // ceil(100000/1024) scan chunks

// g0 SMEM
#define G0_A    0        // [8 planes][64 rows][8 words] = 16384 B
#define G0_WA   16384    // 65536 B
#define G0_WB   81920    // 65536 B
#define G0_B1   147456   // 256 floats
#define SMEM_G0 148480

// g1 SMEM
#define G1_ROWS 0        // 128 int
#define G1_COLS 512      // 128 int
#define G1_EIDX 1024     // 128 int
#define G1_WC   1536     // [4][256][8] words = 32768 B
#define G1_AEA  34304    // [4][128][8] words = 16384 B
#define G1_UV   50688    // 128 rows x 136 words x 4 B = 69632 B
#define SMEM_G1 120320

// g2 SMEM
#define F_B2_OFF   0
#define F_ABUF_OFF 1024  // 2 x 8192
#define F_W2_OFF   17408 // 65536
#define SMEM_FIN   82944

// ============================================================================
// Device scratch (allocation-free)
// ============================================================================
__device__ __align__(16) __half g_Wa[8 * 2048 * 2];
__device__ __align__(16) __half g_Wb[8 * 2048 * 2];
__device__ __align__(16) __half g_Wc[4 * 2048 * 2];
__device__ __align__(16) __half g_W2h[8 * 4096];
__device__ __align__(16) __half g_u[NN_NODES * 256];
__device__ __align__(16) __half g_v[NN_NODES * 256];
__device__ __align__(16) __half g_hsumh[NN_NODES * 256];   // fp16 hsum
__device__ float g_degf[NN_NODES];
__device__ int   g_is64;
// counting-sort scratch
__device__ int g_cnt[NN_NODES];
__device__ int g_off[NN_NODES];
__device__ int g_blksum[NCHUNKS];
__device__ int g_rows_srt[E_TOTAL];
__device__ int g_cols_srt[E_TOTAL];
__device__ int g_eidx_srt[E_TOTAL];

// ============================================================================
// Helpers
// ============================================================================
__device__ __forceinline__ uint32_t f2h2(float lo, float hi) {
    uint32_t r;
    asm("cvt.rn.f16x2.f32 %0, %1, %2;" : "=r"(r) : "f"(hi), "f"(lo));
    return r;
}
__device__ __forceinline__ uint32_t hadd2u(uint32_t a, uint32_t b) {
    uint32_t r;
    asm("add.rn.f16x2 %0, %1, %2;" : "=r"(r) : "r"(a), "r"(b));
    return r;
}
__device__ __forceinline__ void mma16(float* d, const uint32_t* a,
                                      uint32_t b0, uint32_t b1) {
    asm volatile(
        "mma.sync.aligned.m16n8k16.row.col.f32.f16.f16.f32 "
        "{%0,%1,%2,%3}, {%4,%5,%6,%7}, {%8,%9}, {%0,%1,%2,%3};"
        : "+f"(d[0]), "+f"(d[1]), "+f"(d[2]), "+f"(d[3])
        : "r"(a[0]), "r"(a[1]), "r"(a[2]), "r"(a[3]), "r"(b0), "r"(b1));
}
__device__ __forceinline__ void redh2(__half* p, float lo, float hi) {
    uint32_t v = f2h2(lo, hi);
    asm volatile("red.global.add.noftz.f16x2 [%0], %1;"
                 :: "l"(p), "r"(v) : "memory");
}
__device__ __forceinline__ int ld_idx(const void* ei, int pos) {
    return g_is64 ? (int)((const long long*)ei)[pos] : ((const int*)ei)[pos];
}

// Stage 16 consecutive k-values (one k16 plane, f32 inputs) of one row.
// word = ks*stride + row*8 + ((2s)^z) + hi, z = (row&4) ^ ((ks&1)<<1).
__device__ __forceinline__ void stage_row(uint32_t* ab, int row, int ks,
                                          int stride, const float4* v) {
    uint32_t* rp = ab + ks * stride + row * 8;
    const int z = (row & 4) ^ ((ks & 1) << 1);
    *(uint2*)&rp[0 ^ z] = make_uint2(f2h2(v[0].x, v[0].y), f2h2(v[2].x, v[2].y));
    *(uint2*)&rp[2 ^ z] = make_uint2(f2h2(v[0].z, v[0].w), f2h2(v[2].z, v[2].w));
    *(uint2*)&rp[4 ^ z] = make_uint2(f2h2(v[1].x, v[1].y), f2h2(v[3].x, v[3].y));
    *(uint2*)&rp[6 ^ z] = make_uint2(f2h2(v[1].z, v[1].w), f2h2(v[3].z, v[3].w));
}
// Same, fp16 inputs: a = k-pairs w0..w3, b = w4..w7.
__device__ __forceinline__ void stage_row_h(uint32_t* ab, int row, int ks,
                                            int stride, uint4 a, uint4 b) {
    uint32_t* rp = ab + ks * stride + row * 8;
    const int z = (row & 4) ^ ((ks & 1) << 1);
    *(uint2*)&rp[0 ^ z] = make_uint2(a.x, b.x);
    *(uint2*)&rp[2 ^ z] = make_uint2(a.y, b.y);
    *(uint2*)&rp[4 ^ z] = make_uint2(a.z, b.z);
    *(uint2*)&rp[6 ^ z] = make_uint2(a.w, b.w);
}

// Matching weight-image element store (setup side).
__device__ __forceinline__ void img_store(__half* img, int kk, int n,
                                          int plane_words, float val) {
    const int ks = kk >> 4, w = (kk & 15) >> 1;
    const int z = (n & 4) ^ ((ks & 1) << 1);
    const int word = ks * plane_words + n * 8 + ((2 * (w & 3)) ^ z) + (w >> 2);
    img[word * 2 + (kk & 1)] = __float2half_rn(val);
}

// ============================================================================
// Setup + counting sort
// ============================================================================
#define SETUP_BLOCKS 13350
__global__ void setup_kernel(const void* ei, const float* __restrict__ W1,
                             const float* __restrict__ W2) {
    int i = blockIdx.x * 256 + threadIdx.x;
    if (i < 3200000) {   // zero fp16 hsum: 100000*256 halves = 3.2M uint4
        ((uint4*)g_hsumh)[i] = make_uint4(0, 0, 0, 0);
        return;
    }
    i -= 3200000;
    if (i < NN_NODES) { g_cnt[i] = 0; return; }
    i -= NN_NODES;
    if (i < 32768) {                       // W1a
        int kk = i >> 8, n = i & 255;
        img_store(g_Wa, kk, n, 2048, W1[kk * 256 + n]);
    } else if (i < 65536) {                // W1b
        int j = i - 32768;
        int kk = j >> 8, n = j & 255;
        img_store(g_Wb, kk, n, 2048, W1[(kk + 128) * 256 + n]);
    } else if (i < 81920) {                // W1c
        int j = i - 65536;
        int kk = j >> 8, n = j & 255;
        img_store(g_Wc, kk, n, 2048, W1[(kk + 256) * 256 + n]);
    } else if (i < 114688) {               // W2
        int j = i - 81920;
        int k = j >> 7, n = j & 127;
        img_store(g_W2h + (k >> 5) * 4096, k & 31, n, 1024, W2[k * 128 + n]);
    } else if (i == 114688) {              // int64 probe
        const unsigned* w = (const unsigned*)ei;
        int is64 = 1;
        for (int t = 0; t < 64; t++)
            if (w[2 * t + 1] != 0) { is64 = 0; break; }
        g_is64 = is64;
    }
}

__global__ void hist_kernel(const void* ei) {
    int e = blockIdx.x * 256 + threadIdx.x;
    if (e < E_TOTAL) atomicAdd(&g_cnt[ld_idx(ei, e)], 1);
}

__global__ void scan1_kernel() {
    __shared__ int s[1024];
    int g = blockIdx.x * 1024 + threadIdx.x;
    int v = (g < NN_NODES) ? g_cnt[g] : 0;
    s[threadIdx.x] = v;
    __syncthreads();
    #pragma unroll
    for (int d = 1; d < 1024; d <<= 1) {
        int t = (threadIdx.x >= d) ? s[threadIdx.x - d] : 0;
        __syncthreads();
        s[threadIdx.x] += t;
        __syncthreads();
    }
    if (g < NN_NODES) {
        g_off[g] = s[threadIdx.x] - v;
        g_degf[g] = (float)v;
    }
    if (threadIdx.x == 1023) g_blksum[blockIdx.x] = s[1023];
}

__global__ void scan2_kernel() {
    if (threadIdx.x == 0) {
        int acc = 0;
        for (int i = 0; i < NCHUNKS; i++) {
            int t = g_blksum[i];
            g_blksum[i] = acc;
            acc += t;
        }
    }
}

__global__ void scan3_kernel() {
    int g = blockIdx.x * 256 + threadIdx.x;
    if (g < NN_NODES) {
        int o = g_off[g] + g_blksum[g >> 10];
        g_off[g] = o;
        g_cnt[g] = o;
    }
}

__global__ void place_kernel(const void* ei) {
    int e = blockIdx.x * 256 + threadIdx.x;
    if (e < E_TOTAL) {
        int r = ld_idx(ei, e);
        int c = ld_idx(ei, E_TOTAL + e);
        int pos = atomicAdd(&g_cnt[r], 1);
        g_rows_srt[pos] = r;
        g_cols_srt[pos] = c;
        g_eidx_srt[pos] = e;
    }
}

// ============================================================================
// g0: u[n] = fp16(x[n]@W1a + b1), v[n] = fp16(x[n]@W1b).  (unchanged)
// ============================================================================
__global__ void __launch_bounds__(256, 1)
edgeconv_g0(const float* __restrict__ x, const float* __restrict__ b1) {
    extern __shared__ char smem[];
    const int tid  = threadIdx.x;
    const int wid  = tid >> 5;
    const int lane = tid & 31;
    const int gq   = lane >> 2;
    const int q2   = 2 * (lane & 3);
    const int zn   = gq & 4;
    const int rowg = wid & 1;
    const int colh = (wid >> 1) & 1;
    const int outs = wid >> 2;

    {
        const float4* sa = (const float4*)g_Wa;
        const float4* sb = (const float4*)g_Wb;
        float4* da = (float4*)(smem + G0_WA);
        float4* db = (float4*)(smem + G0_WB);
        #pragma unroll
        for (int i = 0; i < 16; i++) {
            da[tid + i * 256] = sa[tid + i * 256];
            db[tid + i * 256] = sb[tid + i * 256];
        }
        ((float*)(smem + G0_B1))[tid] = b1[tid];
    }
    __syncthreads();

    float2 b1v[16];
    #pragma unroll
    for (int nt = 0; nt < 16; nt++)
        b1v[nt] = *(const float2*)((float*)(smem + G0_B1) +
                                   128 * colh + 8 * nt + 2 * (lane & 3));

    const int rbase = 32 * rowg + gq;
    const int e   = tid >> 2;
    const int sub = tid & 3;
    uint32_t* Axw = (uint32_t*)(smem + G0_A);
    const uint32_t* Wim = (const uint32_t*)(smem + (outs ? G0_WB : G0_WA));

    for (int tile = blockIdx.x; tile < N_TILES0; tile += GRID_MAIN) {
        const int grow = tile * 64 + e;
        const bool gok = grow < NN_NODES;
        __syncthreads();
        #pragma unroll
        for (int pi = 0; pi < 2; pi++) {
            const int p = 2 * sub + pi;
            float4 v[4];
            const float* sp = x + (size_t)grow * 128 + p * 16;
            #pragma unroll
            for (int j = 0; j < 4; j++)
                v[j] = gok ? *(const float4*)(sp + j * 4) : make_float4(0, 0, 0, 0);
            stage_row(Axw, e, p, 512, v);
        }
        __syncthreads();

        float acc[2][16][4];
        #pragma unroll
        for (int mt = 0; mt < 2; mt++)
            #pragma unroll
            for (int nt = 0; nt < 16; nt++) {
                float bx = outs ? 0.f : b1v[nt].x;
                float by = outs ? 0.f : b1v[nt].y;
                acc[mt][nt][0] = bx; acc[mt][nt][1] = by;
                acc[mt][nt][2] = bx; acc[mt][nt][3] = by;
            }

        #pragma unroll
        for (int ks = 0; ks < 8; ks++) {
            const uint32_t* Aks = Axw + ks * 512;
            const uint32_t* Bks = Wim + ks * 2048;
            const int qz = q2 ^ zn ^ ((ks & 1) << 1);
            uint32_t af[2][4];
            #pragma unroll
            for (int mt = 0; mt < 2; mt++) {
                const int r0 = rbase + 16 * mt;
                uint2 lo = *(const uint2*)&Aks[r0 * 8 + qz];
                uint2 hi = *(const uint2*)&Aks[(r0 + 8) * 8 + qz];
                af[mt][0] = lo.x; af[mt][1] = hi.x;
                af[mt][2] = lo.y; af[mt][3] = hi.y;
            }
            #pragma unroll
            for (int nt = 0; nt < 16; nt++) {
                const int n = 128 * colh + 8 * nt + gq;
                uint2 bv = *(const uint2*)&Bks[n * 8 + qz];
                #pragma unroll
                for (int mt = 0; mt < 2; mt++) mma16(acc[mt][nt], af[mt], bv.x, bv.y);
            }
        }

        __half* outp = outs ? g_v : g_u;
        #pragma unroll
        for (int mt = 0; mt < 2; mt++) {
            const int r0 = tile * 64 + rbase + 16 * mt;
            #pragma unroll
            for (int nt = 0; nt < 16; nt++) {
                const int cn = 128 * colh + 8 * nt + 2 * (lane & 3);
                if (r0 < NN_NODES)
                    *(uint32_t*)(outp + (size_t)r0 * 256 + cn) =
                        f2h2(acc[mt][nt][0], acc[mt][nt][1]);
                if (r0 + 8 < NN_NODES)
                    *(uint32_t*)(outp + (size_t)(r0 + 8) * 256 + cn) =
                        f2h2(acc[mt][nt][2], acc[mt][nt][3]);
            }
        }
    }
}

// ============================================================================
// g1: dest-sorted edges; ea@W1c GEMM; h -> fp16 in-place in UV; run-aggregated
//     (f32 regs) scatter via fp16 RED into g_hsumh.
// ============================================================================
__global__ void __launch_bounds__(256, 1)
edgeconv_g1(const float* __restrict__ ea) {
    extern __shared__ char smem[];
    const int tid  = threadIdx.x;
    const int wid  = tid >> 5;
    const int lane = tid & 31;
    const int gq   = lane >> 2;
    const int q2   = 2 * (lane & 3);
    const int zn   = gq & 4;
    const int wr   = wid >> 2;   // rows [64wr, +64)
    const int wc   = wid & 3;    // cols [64wc, +64)

    int* rows_s = (int*)(smem + G1_ROWS);
    int* cols_s = (int*)(smem + G1_COLS);
    int* eidx_s = (int*)(smem + G1_EIDX);
    uint32_t* WC  = (uint32_t*)(smem + G1_WC);
    uint32_t* AEA = (uint32_t*)(smem + G1_AEA);
    uint32_t* UV  = (uint32_t*)(smem + G1_UV);

    {   // resident W1c image (32 KB)
        const float4* src = (const float4*)g_Wc;
        float4* dst = (float4*)(smem + G1_WC);
        #pragma unroll
        for (int i = 0; i < 8; i++) dst[tid + i * 256] = src[tid + i * 256];
    }

    const int rbase = 64 * wr + gq;
    const int e  = tid >> 1;
    const int h  = tid & 1;
    const int e2 = (e >> 2) & 1;
    const int hh68 = 68 * (wc >> 1);
    const int wbase = 32 * (wc & 1) + (lane & 3);
    const int g4 = gq & 4;
    const int m_  = lane & 3;
    const int jlA = lane >> 2;

    for (int tile = blockIdx.x; tile < N_TILES; tile += GRID_MAIN) {
        const int ebase = tile * TILE_E;
        __syncthreads();
        if (tid < 128) {
            rows_s[tid] = g_rows_srt[ebase + tid];
            cols_s[tid] = g_cols_srt[ebase + tid];
            eidx_s[tid] = g_eidx_srt[ebase + tid];
        }
        __syncthreads();

        // stage ea chunk via sorted edge index
        #pragma unroll
        for (int pi = 0; pi < 2; pi++) {
            const int p = 2 * h + pi;
            float4 v[4];
            const float* sp = ea + (size_t)eidx_s[e] * 64 + p * 16;
            #pragma unroll
            for (int j = 0; j < 4; j++) v[j] = *(const float4*)(sp + j * 4);
            stage_row(AEA, e, p, 1024, v);
        }
        // stage uv = u[row]+v[col]
        {
            const __half* up = g_u + (size_t)rows_s[e] * 256;
            const __half* vp = g_v + (size_t)cols_s[e] * 256;
            uint32_t* uvrow = UV + e * 136 + 68 * h;
            #pragma unroll
            for (int j = 0; j < 16; j++) {
                const int lg = 16 * h + (j ^ e2);
                uint4 a = *(const uint4*)(up + lg * 8);
                uint4 b = *(const uint4*)(vp + lg * 8);
                uint4 r;
                r.x = hadd2u(a.x, b.x); r.y = hadd2u(a.y, b.y);
                r.z = hadd2u(a.z, b.z); r.w = hadd2u(a.w, b.w);
                *(uint4*)(uvrow + 4 * j) = r;
            }
        }
        __syncthreads();

        // ea GEMM: K=64 -> 4 k16 planes
        float acc[4][8][4];
        #pragma unroll
        for (int mt = 0; mt < 4; mt++)
            #pragma unroll
            for (int nt = 0; nt < 8; nt++)
                #pragma unroll
                for (int i = 0; i < 4; i++) acc[mt][nt][i] = 0.f;

        #pragma unroll
        for (int ks = 0; ks < 4; ks++) {
            const uint32_t* Aks = AEA + ks * 1024;
            const uint32_t* Bks = WC + ks * 2048;
            const int qz = q2 ^ zn ^ ((ks & 1) << 1);
            uint32_t af[4][4];
            #pragma unroll
            for (int mt = 0; mt < 4; mt++) {
                const int r0 = rbase + 16 * mt;
                uint2 lo = *(const uint2*)&Aks[r0 * 8 + qz];
                uint2 hi = *(const uint2*)&Aks[(r0 + 8) * 8 + qz];
                af[mt][0] = lo.x; af[mt][1] = hi.x;
                af[mt][2] = lo.y; af[mt][3] = hi.y;
            }
            #pragma unroll
            for (int nt = 0; nt < 8; nt++) {
                const int n = 64 * wc + 8 * nt + gq;
                uint2 bv = *(const uint2*)&Bks[n * 8 + qz];
                #pragma unroll
                for (int mt = 0; mt < 4; mt++) mma16(acc[mt][nt], af[mt], bv.x, bv.y);
            }
        }

        // epilogue: h = relu(acc + uv) -> fp16 back in place (single-owner)
        #pragma unroll
        for (int mt = 0; mt < 4; mt++) {
            const int r0 = rbase + 16 * mt;
            uint32_t* uv0 = UV + r0 * 136 + hh68;
            uint32_t* uv1 = UV + (r0 + 8) * 136 + hh68;
            #pragma unroll
            for (int nt = 0; nt < 8; nt++) {
                const int off = (wbase + 4 * nt) ^ g4;
                float2 f0 = __half22float2(*(const __half2*)&uv0[off]);
                float2 f1 = __half22float2(*(const __half2*)&uv1[off]);
                uv0[off] = f2h2(fmaxf(acc[mt][nt][0] + f0.x, 0.f),
                                fmaxf(acc[mt][nt][1] + f0.y, 0.f));
                uv1[off] = f2h2(fmaxf(acc[mt][nt][2] + f1.x, 0.f),
                                fmaxf(acc[mt][nt][3] + f1.y, 0.f));
            }
        }
        __syncthreads();

        // aggregated scatter: warp-per-row; one fp16 RED set per same-dest run
        #pragma unroll 1
        for (int t16 = 0; t16 < 16; t16++) {
            const int r = 16 * wid + t16;
            const int dest = rows_s[r];
            if (r > 0 && rows_s[r - 1] == dest) continue;  // warp-uniform
            float2 s[4];
            #pragma unroll
            for (int t = 0; t < 4; t++) s[t] = make_float2(0.f, 0.f);
            int rr = r;
            do {
                const int e2r = (rr >> 2) & 1;
                const uint32_t* rowp = UV + rr * 136;
                #pragma unroll
                for (int t = 0; t < 4; t++) {
                    const int h_ = t & 1;
                    const int jl = jlA + 8 * (t >> 1);
                    const int w  = 4 * (jl ^ e2r) + m_;
                    float2 f = __half22float2(*(const __half2*)&rowp[68 * h_ + w]);
                    s[t].x += f.x; s[t].y += f.y;
                }
                rr++;
            } while (rr < 128 && rows_s[rr] == dest);
            __half* dst = g_hsumh + (size_t)dest * 256;
            #pragma unroll
            for (int t = 0; t < 4; t++) {
                const int h_ = t & 1;
                const int jl = jlA + 8 * (t >> 1);
                redh2(dst + 128 * h_ + 8 * jl + 2 * m_, s[t].x, s[t].y);
            }
        }
    }
}

// ============================================================================
// g2: out[n,:] = hsumh[n] @ W2 + degf[n]*b2  (A loads fp16 directly)
// ============================================================================
__global__ void __launch_bounds__(256, 1)
edgeconv_g2(const float* __restrict__ b2, float* __restrict__ out) {
    extern __shared__ char smem[];
    const int tid  = threadIdx.x;
    const int wid  = tid >> 5;
    const int lane = tid & 31;
    const int wr   = wid >> 1;
    const int wc   = wid & 1;
    const int gq   = lane >> 2;
    const int q2   = 2 * (lane & 3);
    const int zn   = gq & 4;

    float* sB2 = (float*)(smem + F_B2_OFF);
    if (tid < 128) sB2[tid] = b2[tid];
    {
        const float4* src = (const float4*)g_W2h;
        float4* dst = (float4*)(smem + F_W2_OFF);
        #pragma unroll
        for (int i = 0; i < 16; i++) dst[tid + i * 256] = src[tid + i * 256];
    }
    __syncthreads();

    float2 b2v[8];
    #pragma unroll
    for (int nt = 0; nt < 8; nt++)
        b2v[nt] = *(const float2*)&sB2[64 * wc + 8 * nt + 2 * (lane & 3)];

    const int rbase = 32 * wr + gq;
    const int e     = tid >> 1;
    const int half  = tid & 1;

    for (int tile = blockIdx.x; tile < N_TILES2; tile += GRID_MAIN) {
        const int rg = tile * 128 + e;
        const bool ok = rg < NN_NODES;
        const __half* hrow = g_hsumh + (size_t)rg * 256;
        uint4 va, vb;
        const uint4 zz = make_uint4(0, 0, 0, 0);
        {   // chunk 0 -> smem; chunk 1 -> regs (16 halves per plane each)
            const __half* p = hrow + 16 * half;
            va = ok ? *(const uint4*)p : zz;
            vb = ok ? *(const uint4*)(p + 8) : zz;
            stage_row_h((uint32_t*)(smem + F_ABUF_OFF), e, half, 1024, va, vb);
            p = hrow + 32 + 16 * half;
            va = ok ? *(const uint4*)p : zz;
            vb = ok ? *(const uint4*)(p + 8) : zz;
        }
        __syncthreads();

        float acc[2][8][4];
        #pragma unroll
        for (int mt = 0; mt < 2; mt++)
            #pragma unroll
            for (int nt = 0; nt < 8; nt++)
                #pragma unroll
                for (int i = 0; i < 4; i++) acc[mt][nt][i] = 0.f;

        #pragma unroll 1
        for (int j = 0; j < 8; j++) {
            const int s = j & 1;
            const uint32_t* A16 = (const uint32_t*)(smem + F_ABUF_OFF + s * 8192);
            const uint32_t* B16 = (const uint32_t*)(smem + F_W2_OFF + j * 8192);
            #pragma unroll
            for (int ks = 0; ks < 2; ks++) {
                const uint32_t* Aks = A16 + ks * 1024;
                const uint32_t* Bks = B16 + ks * 1024;
                const int qz = q2 ^ zn ^ (ks << 1);
                uint32_t af[2][4];
                #pragma unroll
                for (int mt = 0; mt < 2; mt++) {
                    const int r0 = rbase + 16 * mt;
                    uint2 lo = *(const uint2*)&Aks[r0 * 8 + qz];
                    uint2 hi = *(const uint2*)&Aks[(r0 + 8) * 8 + qz];
                    af[mt][0] = lo.x; af[mt][1] = hi.x;
                    af[mt][2] = lo.y; af[mt][3] = hi.y;
                }
                #pragma unroll
                for (int nt = 0; nt < 8; nt++) {
                    const int n = 64 * wc + 8 * nt + gq;
                    uint2 bv = *(const uint2*)&Bks[n * 8 + qz];
                    #pragma unroll
                    for (int mt = 0; mt < 2; mt++) mma16(acc[mt][nt], af[mt], bv.x, bv.y);
                }
            }
            if (j < 7) {
                stage_row_h((uint32_t*)(smem + F_ABUF_OFF + (s ^ 1) * 8192),
                            e, half, 1024, va, vb);
                if (j < 6) {
                    const __half* p = hrow + (j + 2) * 32 + 16 * half;
                    va = ok ? *(const uint4*)p : zz;
                    vb = ok ? *(const uint4*)(p + 8) : zz;
                }
            }
            __syncthreads();
        }

        #pragma unroll
        for (int mt = 0; mt < 2; mt++) {
            const int r0 = tile * 128 + rbase + 16 * mt;
            const bool ok0 = r0 < NN_NODES;
            const bool ok1 = (r0 + 8) < NN_NODES;
            const float dg0 = ok0 ? g_degf[r0] : 0.f;
            const float dg1 = ok1 ? g_degf[r0 + 8] : 0.f;
            #pragma unroll
            for (int nt = 0; nt < 8; nt++) {
                const int cn = 64 * wc + 8 * nt + 2 * (lane & 3);
                if (ok0) {
                    float2 o = make_float2(acc[mt][nt][0] + dg0 * b2v[nt].x,
                                           acc[mt][nt][1] + dg0 * b2v[nt].y);
                    *(float2*)(out + (size_t)r0 * 128 + cn) = o;
                }
                if (ok1) {
                    float2 o = make_float2(acc[mt][nt][2] + dg1 * b2v[nt].x,
                                           acc[mt][nt][3] + dg1 * b2v[nt].y);
                    *(float2*)(out + (size_t)(r0 + 8) * 128 + cn) = o;
                }
            }
        }
    }
}

// ============================================================================
// Launch
// ============================================================================
extern "C" void kernel_launch(void* const* d_in, const int* in_sizes, int n_in,
                              void* d_out, int out_size) {
    const float* x  = (const float*)d_in[0];
    const void*  ei = d_in[1];
    const float* ea = (const float*)d_in[2];
    const float* W1 = (const float*)d_in[3];
    const float* b1 = (const float*)d_in[4];
    const float* W2 = (const float*)d_in[5];
    const float* b2 = (const float*)d_in[6];
    float* out = (float*)d_out;

    cudaFuncSetAttribute(edgeconv_g0,
                         cudaFuncAttributeMaxDynamicSharedMemorySize, SMEM_G0);
    cudaFuncSetAttribute(edgeconv_g1,
                         cudaFuncAttributeMaxDynamicSharedMemorySize, SMEM_G1);
    cudaFuncSetAttribute(edgeconv_g2,
                         cudaFuncAttributeMaxDynamicSharedMemorySize, SMEM_FIN);

    setup_kernel<<<SETUP_BLOCKS, 256>>>(ei, W1, W2);
    hist_kernel<<<(E_TOTAL + 255) / 256, 256>>>(ei);
    scan1_kernel<<<NCHUNKS, 1024>>>();
    scan2_kernel<<<1, 32>>>();
    scan3_kernel<<<(NN_NODES + 255) / 256, 256>>>();
    place_kernel<<<(E_TOTAL + 255) / 256, 256>>>(ei);
    edgeconv_g0<<<GRID_MAIN, 256, SMEM_G0>>>(x, b1);
    edgeconv_g1<<<GRID_MAIN, 256, SMEM_G1>>>(ea);
    edgeconv_g2<<<GRID_MAIN, 256, SMEM_FIN>>>(b2, out);
}